// round 1
// baseline (speedup 1.0000x reference)
#include <cuda_runtime.h>
#include <math.h>

// Problem constants
#define BW    1024          // windows (batch)
#define NTOK  64            // tokens per window (8x8)
#define CDIM  512           // channels
#define HEADS 16
#define HD    32            // head dim
#define BNC   (BW*NTOK*CDIM)   // 33554432 elements per buffer

// Scratch: 6 slots x 128MB = 805MB device-global (no allocation APIs allowed).
// slot 0: dwq (later reused for attention output)
// slot 1: dwk   slot 2: dwv
// slot 3: q     slot 4: k     slot 5: v
__device__ float g_scr[6][BNC];

// ---------------------------------------------------------------------------
// Kernel 1: fused depthwise 3x3 (+bias, ReLU) for q, k, v.
// Each block: one window b, one 128-channel chunk. x tile staged in smem once.
// Output layout: [b, n, c]  (c contiguous -> GEMM A matrix)
// ---------------------------------------------------------------------------
__global__ void dw3_kernel(const float* __restrict__ x,
                           const float* __restrict__ wq, const float* __restrict__ bq,
                           const float* __restrict__ wk, const float* __restrict__ bk,
                           const float* __restrict__ wv, const float* __restrict__ bv)
{
    const int b   = blockIdx.y;
    const int c0  = blockIdx.x * 128;
    const int tid = threadIdx.x;            // 256 threads

    __shared__ float sx[64][128];
    const float* xb = x + (size_t)b * NTOK * CDIM;

    #pragma unroll
    for (int i = tid; i < 64 * 128; i += 256) {
        int n = i >> 7, c = i & 127;
        sx[n][c] = xb[n * CDIM + c0 + c];
    }
    __syncthreads();

    const int cl   = tid & 127;             // local channel
    const int c    = c0 + cl;               // global channel
    const int half = tid >> 7;              // 0 or 1 (n in [0,32) or [32,64))

    float wqr[9], wkr[9], wvr[9];
    #pragma unroll
    for (int j = 0; j < 9; ++j) {
        wqr[j] = wq[c * 9 + j];
        wkr[j] = wk[c * 9 + j];
        wvr[j] = wv[c * 9 + j];
    }
    const float bqr = bq[c], bkr = bk[c], bvr = bv[c];

    float* oq = g_scr[0] + (size_t)b * NTOK * CDIM;
    float* ok = g_scr[1] + (size_t)b * NTOK * CDIM;
    float* ov = g_scr[2] + (size_t)b * NTOK * CDIM;

    #pragma unroll 4
    for (int nn = 0; nn < 32; ++nn) {
        int n = half * 32 + nn;
        int l = n >> 3, w = n & 7;
        float aq = bqr, ak = bkr, av = bvr;
        #pragma unroll
        for (int dl = -1; dl <= 1; ++dl) {
            #pragma unroll
            for (int dw = -1; dw <= 1; ++dw) {
                int ll = l + dl, ww = w + dw;
                if (ll < 0 || ll > 7 || ww < 0 || ww > 7) continue;
                float xv = sx[ll * 8 + ww][cl];
                int j = (dl + 1) * 3 + (dw + 1);
                aq += xv * wqr[j];
                ak += xv * wkr[j];
                av += xv * wvr[j];
            }
        }
        int idx = n * CDIM + c;
        oq[idx] = fmaxf(aq, 0.0f);
        ok[idx] = fmaxf(ak, 0.0f);
        ov[idx] = fmaxf(av, 0.0f);
    }
}

// ---------------------------------------------------------------------------
// Kernel 2: fp32 SGEMM  C[M,512] = A[M,512] @ W[512,512]^T + bias
// A = g_scr[aslot]; C = Cout (if non-null) else g_scr[cslot].
// 128x128x8 block tile, 256 threads, 8x8 per-thread microtile.
// M = 65536 (divisible by 128), N = K = 512 -> no bounds checks needed.
// ---------------------------------------------------------------------------
__global__ void __launch_bounds__(256, 2)
gemm_abt(int aslot, const float* __restrict__ W,
         const float* __restrict__ bias, int cslot, float* __restrict__ Cout)
{
    const int K = 512, NN = 512;
    const float* A = g_scr[aslot];
    float* C = Cout ? Cout : g_scr[cslot];

    __shared__ float As[8][128];
    __shared__ float Bs[8][128];

    const int tid = threadIdx.x;
    const int m0 = blockIdx.y * 128;
    const int n0 = blockIdx.x * 128;

    const int lr = tid >> 1;          // 0..127 (row within tile)
    const int lc = (tid & 1) * 4;     // 0 or 4 (k offset)

    const float* Ap = A + (size_t)(m0 + lr) * K + lc;
    const float* Bp = W + (size_t)(n0 + lr) * K + lc;

    const int ty = tid >> 4;          // 0..15
    const int tx = tid & 15;          // 0..15

    float acc[8][8];
    #pragma unroll
    for (int i = 0; i < 8; ++i)
        #pragma unroll
        for (int j = 0; j < 8; ++j) acc[i][j] = 0.0f;

    for (int k0 = 0; k0 < K; k0 += 8) {
        float4 av = *(const float4*)(Ap + k0);
        float4 bv = *(const float4*)(Bp + k0);
        As[lc + 0][lr] = av.x; As[lc + 1][lr] = av.y;
        As[lc + 2][lr] = av.z; As[lc + 3][lr] = av.w;
        Bs[lc + 0][lr] = bv.x; Bs[lc + 1][lr] = bv.y;
        Bs[lc + 2][lr] = bv.z; Bs[lc + 3][lr] = bv.w;
        __syncthreads();

        #pragma unroll
        for (int kk = 0; kk < 8; ++kk) {
            float a[8], bb[8];
            float4 a0 = *(const float4*)&As[kk][ty * 8];
            float4 a1 = *(const float4*)&As[kk][ty * 8 + 4];
            float4 b0 = *(const float4*)&Bs[kk][tx * 8];
            float4 b1 = *(const float4*)&Bs[kk][tx * 8 + 4];
            a[0]=a0.x; a[1]=a0.y; a[2]=a0.z; a[3]=a0.w;
            a[4]=a1.x; a[5]=a1.y; a[6]=a1.z; a[7]=a1.w;
            bb[0]=b0.x; bb[1]=b0.y; bb[2]=b0.z; bb[3]=b0.w;
            bb[4]=b1.x; bb[5]=b1.y; bb[6]=b1.z; bb[7]=b1.w;
            #pragma unroll
            for (int i = 0; i < 8; ++i)
                #pragma unroll
                for (int j = 0; j < 8; ++j)
                    acc[i][j] += a[i] * bb[j];
        }
        __syncthreads();
    }

    // Epilogue: add bias, vectorized stores
    #pragma unroll
    for (int i = 0; i < 8; ++i) {
        int m = m0 + ty * 8 + i;
        float* Cp = C + (size_t)m * NN + n0 + tx * 8;
        const float* bp = bias + n0 + tx * 8;
        float4 o0, o1;
        o0.x = acc[i][0] + bp[0]; o0.y = acc[i][1] + bp[1];
        o0.z = acc[i][2] + bp[2]; o0.w = acc[i][3] + bp[3];
        o1.x = acc[i][4] + bp[4]; o1.y = acc[i][5] + bp[5];
        o1.z = acc[i][6] + bp[6]; o1.w = acc[i][7] + bp[7];
        *(float4*)(Cp + 0) = o0;
        *(float4*)(Cp + 4) = o1;
    }
}

// ---------------------------------------------------------------------------
// Kernel 3: attention per (b, h). 64 threads, thread n owns output row n.
// q/k/v from slots 3/4/5; output (softmax(qk^T*scale+pos+mask) @ v) -> slot 0.
// ---------------------------------------------------------------------------
__global__ void __launch_bounds__(64)
attn_kernel(const float* __restrict__ pos, const float* __restrict__ mask)
{
    const int bh = blockIdx.x;
    const int b = bh >> 4;
    const int h = bh & 15;
    const int n = threadIdx.x;   // 0..63

    __shared__ float ks[64][32];
    __shared__ float vs[64][32];
    __shared__ float qs[64][33]; // pad 33 to kill bank conflicts on row reads

    const float* Q = g_scr[3];
    const float* Kt = g_scr[4];
    const float* V = g_scr[5];
    const size_t base = (size_t)b * 64 * 512 + h * 32;

    #pragma unroll
    for (int i = n; i < 64 * 32; i += 64) {
        int m = i >> 5, d = i & 31;
        size_t g = base + (size_t)m * 512 + d;
        ks[m][d] = Kt[g];
        vs[m][d] = V[g];
        qs[m][d] = Q[g];
    }
    __syncthreads();

    const float scale = 0.17677669529663687f; // (512/16)^-0.5 = 1/sqrt(32)
    float qr[32];
    #pragma unroll
    for (int d = 0; d < 32; ++d) qr[d] = qs[n][d] * scale;

    const float* pr = pos + n * 64;
    const float* mr = mask + ((size_t)b * 64 + n) * 64;

    float s[64];
    float mx = -1e30f;
    #pragma unroll
    for (int m = 0; m < 64; ++m) {
        float acc = 0.0f;
        #pragma unroll
        for (int d = 0; d < 32; ++d) acc += qr[d] * ks[m][d];
        acc += pr[m] + mr[m];
        s[m] = acc;
        mx = fmaxf(mx, acc);
    }
    float sum = 0.0f;
    #pragma unroll
    for (int m = 0; m < 64; ++m) {
        s[m] = expf(s[m] - mx);
        sum += s[m];
    }
    const float inv = 1.0f / sum;

    float o[32];
    #pragma unroll
    for (int d = 0; d < 32; ++d) o[d] = 0.0f;
    #pragma unroll
    for (int m = 0; m < 64; ++m) {
        float p = s[m];
        #pragma unroll
        for (int d = 0; d < 32; ++d) o[d] += p * vs[m][d];
    }

    float* Op = g_scr[0] + base + (size_t)n * 512;
    #pragma unroll
    for (int d = 0; d < 32; d += 4) {
        float4 w;
        w.x = o[d + 0] * inv; w.y = o[d + 1] * inv;
        w.z = o[d + 2] * inv; w.w = o[d + 3] * inv;
        *(float4*)(Op + d) = w;
    }
}

// ---------------------------------------------------------------------------
// Launch
// ---------------------------------------------------------------------------
extern "C" void kernel_launch(void* const* d_in, const int* in_sizes, int n_in,
                              void* d_out, int out_size)
{
    const float* x      = (const float*)d_in[0];
    const float* mask   = (const float*)d_in[1];
    const float* dwq_w  = (const float*)d_in[2];
    const float* dwq_b  = (const float*)d_in[3];
    const float* pwq_w  = (const float*)d_in[4];
    const float* pwq_b  = (const float*)d_in[5];
    const float* dwk_w  = (const float*)d_in[6];
    const float* dwk_b  = (const float*)d_in[7];
    const float* pwk_w  = (const float*)d_in[8];
    const float* pwk_b  = (const float*)d_in[9];
    const float* dwv_w  = (const float*)d_in[10];
    const float* dwv_b  = (const float*)d_in[11];
    const float* pwv_w  = (const float*)d_in[12];
    const float* pwv_b  = (const float*)d_in[13];
    const float* pos    = (const float*)d_in[14];
    const float* proj_w = (const float*)d_in[15];
    const float* proj_b = (const float*)d_in[16];

    // 1. depthwise 3x3 + ReLU for q,k,v  -> slots 0,1,2
    dim3 gdw(4, BW);
    dw3_kernel<<<gdw, 256>>>(x, dwq_w, dwq_b, dwk_w, dwk_b, dwv_w, dwv_b);

    // 2. pointwise GEMMs -> slots 3,4,5
    dim3 gg(512 / 128, (BW * NTOK) / 128);   // (4, 512)
    gemm_abt<<<gg, 256>>>(0, pwq_w, pwq_b, 3, nullptr);
    gemm_abt<<<gg, 256>>>(1, pwk_w, pwk_b, 4, nullptr);
    gemm_abt<<<gg, 256>>>(2, pwv_w, pwv_b, 5, nullptr);

    // 3. attention -> slot 0 (dwq dead by now)
    attn_kernel<<<BW * HEADS, 64>>>(pos, mask);

    // 4. output projection -> d_out
    gemm_abt<<<gg, 256>>>(0, proj_w, proj_b, 0, (float*)d_out);
}

// round 3
// speedup vs baseline: 1.6025x; 1.6025x over previous
#include <cuda_runtime.h>
#include <math.h>
#include <stdint.h>

// Problem constants
#define BW    1024          // windows (batch)
#define NTOK  64            // tokens per window (8x8)
#define CDIM  512           // channels
#define HEADS 16
#define HD    32            // head dim
#define BNC   (BW*NTOK*CDIM)

// Scratch slots (no allocation APIs allowed):
// slot 0: dwq -> later attention output
// slot 1: dwk   slot 2: dwv
// slot 3: q     slot 4: k     slot 5: v
__device__ float g_scr[6][BNC];
// tf32-rounded weights: 0=pwq, 1=pwk, 2=pwv, 3=proj
__device__ float g_w[4][CDIM*CDIM];

__device__ __forceinline__ float tf32r(float x) {
    uint32_t r;
    asm("cvt.rna.tf32.f32 %0, %1;" : "=r"(r) : "f"(x));
    return __uint_as_float(r);
}

// ---------------------------------------------------------------------------
// Weight prep: round 4x [512,512] fp32 weights to tf32 (round-to-nearest).
// ---------------------------------------------------------------------------
__global__ void prep_w(const float* __restrict__ w0, const float* __restrict__ w1,
                       const float* __restrict__ w2, const float* __restrict__ w3)
{
    int idx = blockIdx.x * 256 + threadIdx.x;   // 4*262144 total
    int w = idx >> 18, j = idx & 262143;
    const float* s = (w == 0) ? w0 : (w == 1) ? w1 : (w == 2) ? w2 : w3;
    g_w[w][j] = tf32r(s[j]);
}

// ---------------------------------------------------------------------------
// Kernel 1: fused depthwise 3x3 (+bias, ReLU) for q, k, v. Outputs rounded to
// tf32 (they feed tensor-core GEMMs). Layout [b, n, c].
// ---------------------------------------------------------------------------
__global__ void dw3_kernel(const float* __restrict__ x,
                           const float* __restrict__ wq, const float* __restrict__ bq,
                           const float* __restrict__ wk, const float* __restrict__ bk,
                           const float* __restrict__ wv, const float* __restrict__ bv)
{
    const int b   = blockIdx.y;
    const int c0  = blockIdx.x * 128;
    const int tid = threadIdx.x;            // 256 threads

    __shared__ float sx[64][128];
    const float* xb = x + (size_t)b * NTOK * CDIM;

    #pragma unroll
    for (int i = tid; i < 64 * 128; i += 256) {
        int n = i >> 7, c = i & 127;
        sx[n][c] = xb[n * CDIM + c0 + c];
    }
    __syncthreads();

    const int cl   = tid & 127;
    const int c    = c0 + cl;
    const int half = tid >> 7;

    float wqr[9], wkr[9], wvr[9];
    #pragma unroll
    for (int j = 0; j < 9; ++j) {
        wqr[j] = wq[c * 9 + j];
        wkr[j] = wk[c * 9 + j];
        wvr[j] = wv[c * 9 + j];
    }
    const float bqr = bq[c], bkr = bk[c], bvr = bv[c];

    float* oq = g_scr[0] + (size_t)b * NTOK * CDIM;
    float* ok = g_scr[1] + (size_t)b * NTOK * CDIM;
    float* ov = g_scr[2] + (size_t)b * NTOK * CDIM;

    #pragma unroll 4
    for (int nn = 0; nn < 32; ++nn) {
        int n = half * 32 + nn;
        int l = n >> 3, w = n & 7;
        float aq = bqr, ak = bkr, av = bvr;
        #pragma unroll
        for (int dl = -1; dl <= 1; ++dl) {
            #pragma unroll
            for (int dw = -1; dw <= 1; ++dw) {
                int ll = l + dl, ww = w + dw;
                if (ll < 0 || ll > 7 || ww < 0 || ww > 7) continue;
                float xv = sx[ll * 8 + ww][cl];
                int j = (dl + 1) * 3 + (dw + 1);
                aq += xv * wqr[j];
                ak += xv * wkr[j];
                av += xv * wvr[j];
            }
        }
        int idx = n * CDIM + c;
        oq[idx] = tf32r(fmaxf(aq, 0.0f));
        ok[idx] = tf32r(fmaxf(ak, 0.0f));
        ov[idx] = tf32r(fmaxf(av, 0.0f));
    }
}

// ---------------------------------------------------------------------------
// mma.sync tf32 GEMM: C[65536,512] = A @ W^T + bias
// A = g_scr[aslot] (tf32-rounded), W = g_w[wslot] ([N,K], tf32-rounded).
// CTA 128x128, 4 warps (2x2), warp tile 64x64 via m16n8k8 tf32 mma.sync.
// K-chunk 16, double-buffered smem, rows padded to 20 floats (bank-conflict-
// free quad fragment loads: (m*20+c) mod 32 covers all banks).
// ---------------------------------------------------------------------------
#define PAD 20

__device__ __forceinline__ void mma_tf32(float* d, const float* a, const float* b)
{
    asm volatile(
        "mma.sync.aligned.m16n8k8.row.col.f32.tf32.tf32.f32 "
        "{%0,%1,%2,%3}, {%4,%5,%6,%7}, {%8,%9}, {%0,%1,%2,%3};"
        : "+f"(d[0]), "+f"(d[1]), "+f"(d[2]), "+f"(d[3])
        : "r"(__float_as_uint(a[0])), "r"(__float_as_uint(a[1])),
          "r"(__float_as_uint(a[2])), "r"(__float_as_uint(a[3])),
          "r"(__float_as_uint(b[0])), "r"(__float_as_uint(b[1])));
}

__global__ void __launch_bounds__(128, 2)
gemm_mma(int aslot, int wslot, const float* __restrict__ bias,
         int cslot, float* __restrict__ Cout)
{
    const float* A = g_scr[aslot];
    const float* W = g_w[wslot];
    float* C = Cout ? Cout : g_scr[cslot];

    __shared__ float As[2][128][PAD];
    __shared__ float Bs[2][128][PAD];

    const int tid  = threadIdx.x;
    const int wid  = tid >> 5;
    const int lane = tid & 31;
    const int wm   = wid & 1;        // warp m index (0,1)
    const int wn   = wid >> 1;       // warp n index (0,1)
    const int m0 = blockIdx.y * 128;
    const int n0 = blockIdx.x * 128;

    const int lrow = tid >> 2;       // 0..31  (gmem load row group)
    const int lkq  = tid & 3;        // 0..3   (float4 column)

    const int qrow = lane >> 2;      // 0..7
    const int qcol = lane & 3;       // 0..3

    float acc[4][8][4];
    #pragma unroll
    for (int i = 0; i < 4; ++i)
        #pragma unroll
        for (int j = 0; j < 8; ++j)
            #pragma unroll
            for (int r = 0; r < 4; ++r) acc[i][j][r] = 0.0f;

    const float* Ap = A + (size_t)(m0 + lrow) * 512 + lkq * 4;
    const float* Bp = W + (size_t)(n0 + lrow) * 512 + lkq * 4;

    // prologue: chunk 0 -> stage 0
    {
        #pragma unroll
        for (int i = 0; i < 4; ++i) {
            float4 av = *(const float4*)(Ap + (size_t)(i * 32) * 512);
            float4 bv = *(const float4*)(Bp + (size_t)(i * 32) * 512);
            *(float4*)&As[0][lrow + i * 32][lkq * 4] = av;
            *(float4*)&Bs[0][lrow + i * 32][lkq * 4] = bv;
        }
    }
    __syncthreads();

    #pragma unroll 1
    for (int ch = 0; ch < 32; ++ch) {
        const int s = ch & 1;
        float4 pa[4], pb[4];
        if (ch < 31) {
            const int kb = (ch + 1) * 16;
            #pragma unroll
            for (int i = 0; i < 4; ++i) {
                pa[i] = *(const float4*)(Ap + (size_t)(i * 32) * 512 + kb);
                pb[i] = *(const float4*)(Bp + (size_t)(i * 32) * 512 + kb);
            }
        }

        #pragma unroll
        for (int k8 = 0; k8 < 16; k8 += 8) {
            float a[4][4];
            #pragma unroll
            for (int mi = 0; mi < 4; ++mi) {
                const int mr = wm * 64 + mi * 16 + qrow;
                a[mi][0] = As[s][mr][k8 + qcol];
                a[mi][1] = As[s][mr + 8][k8 + qcol];
                a[mi][2] = As[s][mr][k8 + qcol + 4];
                a[mi][3] = As[s][mr + 8][k8 + qcol + 4];
            }
            float b[8][2];
            #pragma unroll
            for (int ni = 0; ni < 8; ++ni) {
                const int nc = wn * 64 + ni * 8 + qrow;
                b[ni][0] = Bs[s][nc][k8 + qcol];
                b[ni][1] = Bs[s][nc][k8 + qcol + 4];
            }
            #pragma unroll
            for (int mi = 0; mi < 4; ++mi)
                #pragma unroll
                for (int ni = 0; ni < 8; ++ni)
                    mma_tf32(acc[mi][ni], a[mi], b[ni]);
        }

        if (ch < 31) {
            const int ns = s ^ 1;
            #pragma unroll
            for (int i = 0; i < 4; ++i) {
                *(float4*)&As[ns][lrow + i * 32][lkq * 4] = pa[i];
                *(float4*)&Bs[ns][lrow + i * 32][lkq * 4] = pb[i];
            }
        }
        __syncthreads();
    }

    // Epilogue: add bias, float2 stores
    #pragma unroll
    for (int ni = 0; ni < 8; ++ni) {
        const int n = n0 + wn * 64 + ni * 8 + (qcol << 1);
        const float2 bv = *(const float2*)(bias + n);
        #pragma unroll
        for (int mi = 0; mi < 4; ++mi) {
            const int m = m0 + wm * 64 + mi * 16 + qrow;
            float2 o0, o1;
            o0.x = acc[mi][ni][0] + bv.x; o0.y = acc[mi][ni][1] + bv.y;
            o1.x = acc[mi][ni][2] + bv.x; o1.y = acc[mi][ni][3] + bv.y;
            *(float2*)(C + (size_t)m * 512 + n) = o0;
            *(float2*)(C + (size_t)(m + 8) * 512 + n) = o1;
        }
    }
}

// ---------------------------------------------------------------------------
// Kernel 3: attention per (b, h). Output rounded to tf32 (feeds proj GEMM).
// ---------------------------------------------------------------------------
__global__ void __launch_bounds__(64)
attn_kernel(const float* __restrict__ pos, const float* __restrict__ mask)
{
    const int bh = blockIdx.x;
    const int b = bh >> 4;
    const int h = bh & 15;
    const int n = threadIdx.x;

    __shared__ float ks[64][32];
    __shared__ float vs[64][32];
    __shared__ float qs[64][33];

    const float* Q = g_scr[3];
    const float* Kt = g_scr[4];
    const float* V = g_scr[5];
    const size_t base = (size_t)b * 64 * 512 + h * 32;

    #pragma unroll
    for (int i = n; i < 64 * 32; i += 64) {
        int m = i >> 5, d = i & 31;
        size_t g = base + (size_t)m * 512 + d;
        ks[m][d] = Kt[g];
        vs[m][d] = V[g];
        qs[m][d] = Q[g];
    }
    __syncthreads();

    const float scale = 0.17677669529663687f; // 1/sqrt(32)
    float qr[32];
    #pragma unroll
    for (int d = 0; d < 32; ++d) qr[d] = qs[n][d] * scale;

    const float* pr = pos + n * 64;
    const float* mr = mask + ((size_t)b * 64 + n) * 64;

    float s[64];
    float mx = -1e30f;
    #pragma unroll
    for (int m = 0; m < 64; ++m) {
        float acc = 0.0f;
        #pragma unroll
        for (int d = 0; d < 32; ++d) acc += qr[d] * ks[m][d];
        acc += pr[m] + mr[m];
        s[m] = acc;
        mx = fmaxf(mx, acc);
    }
    float sum = 0.0f;
    #pragma unroll
    for (int m = 0; m < 64; ++m) {
        s[m] = expf(s[m] - mx);
        sum += s[m];
    }
    const float inv = 1.0f / sum;

    float o[32];
    #pragma unroll
    for (int d = 0; d < 32; ++d) o[d] = 0.0f;
    #pragma unroll
    for (int m = 0; m < 64; ++m) {
        float p = s[m];
        #pragma unroll
        for (int d = 0; d < 32; ++d) o[d] += p * vs[m][d];
    }

    float* Op = g_scr[0] + base + (size_t)n * 512;
    #pragma unroll
    for (int d = 0; d < 32; d += 4) {
        float4 w;
        w.x = tf32r(o[d + 0] * inv); w.y = tf32r(o[d + 1] * inv);
        w.z = tf32r(o[d + 2] * inv); w.w = tf32r(o[d + 3] * inv);
        *(float4*)(Op + d) = w;
    }
}

// ---------------------------------------------------------------------------
// Launch
// ---------------------------------------------------------------------------
extern "C" void kernel_launch(void* const* d_in, const int* in_sizes, int n_in,
                              void* d_out, int out_size)
{
    const float* x      = (const float*)d_in[0];
    const float* mask   = (const float*)d_in[1];
    const float* dwq_w  = (const float*)d_in[2];
    const float* dwq_b  = (const float*)d_in[3];
    const float* pwq_w  = (const float*)d_in[4];
    const float* pwq_b  = (const float*)d_in[5];
    const float* dwk_w  = (const float*)d_in[6];
    const float* dwk_b  = (const float*)d_in[7];
    const float* pwk_w  = (const float*)d_in[8];
    const float* pwk_b  = (const float*)d_in[9];
    const float* dwv_w  = (const float*)d_in[10];
    const float* dwv_b  = (const float*)d_in[11];
    const float* pwv_w  = (const float*)d_in[12];
    const float* pwv_b  = (const float*)d_in[13];
    const float* pos    = (const float*)d_in[14];
    const float* proj_w = (const float*)d_in[15];
    const float* proj_b = (const float*)d_in[16];

    // 0. round weights to tf32
    prep_w<<<4096, 256>>>(pwq_w, pwk_w, pwv_w, proj_w);

    // 1. depthwise 3x3 + ReLU for q,k,v -> slots 0,1,2 (tf32-rounded)
    dim3 gdw(4, BW);
    dw3_kernel<<<gdw, 256>>>(x, dwq_w, dwq_b, dwk_w, dwk_b, dwv_w, dwv_b);

    // 2. pointwise GEMMs (tensor core via mma.sync) -> slots 3,4,5
    dim3 gg(4, 512);
    gemm_mma<<<gg, 128>>>(0, 0, pwq_b, 3, nullptr);
    gemm_mma<<<gg, 128>>>(1, 1, pwk_b, 4, nullptr);
    gemm_mma<<<gg, 128>>>(2, 2, pwv_b, 5, nullptr);

    // 3. attention -> slot 0 (tf32-rounded)
    attn_kernel<<<BW * HEADS, 64>>>(pos, mask);

    // 4. output projection -> d_out
    gemm_mma<<<gg, 128>>>(0, 3, proj_b, 0, (float*)d_out);
}

// round 5
// speedup vs baseline: 2.3334x; 1.4561x over previous
#include <cuda_runtime.h>
#include <math.h>
#include <stdint.h>

// Problem constants
#define BW    1024          // windows (batch)
#define NTOK  64            // tokens per window (8x8)
#define CDIM  512           // channels
#define HEADS 16
#define HD    32            // head dim
#define BNC   (BW*NTOK*CDIM)

// Scratch slots:
// slot 0: dwq -> later attention output
// slot 1: dwk   slot 2: dwv
// slot 3: q     slot 4: k     slot 5: v
__device__ float g_scr[6][BNC];
// tf32-rounded weights: 0=pwq, 1=pwk, 2=pwv, 3=proj
__device__ float g_w[4][CDIM*CDIM];

__device__ __forceinline__ float tf32r(float x) {
    uint32_t r;
    asm("cvt.rna.tf32.f32 %0, %1;" : "=r"(r) : "f"(x));
    return __uint_as_float(r);
}

// ---------------------------------------------------------------------------
// Weight prep: round 4x [512,512] fp32 weights to tf32.
// ---------------------------------------------------------------------------
__global__ void prep_w(const float* __restrict__ w0, const float* __restrict__ w1,
                       const float* __restrict__ w2, const float* __restrict__ w3)
{
    int idx = blockIdx.x * 256 + threadIdx.x;
    int w = idx >> 18, j = idx & 262143;
    const float* s = (w == 0) ? w0 : (w == 1) ? w1 : (w == 2) ? w2 : w3;
    g_w[w][j] = tf32r(s[j]);
}

// ---------------------------------------------------------------------------
// Kernel 1: fused depthwise 3x3 (+bias, ReLU) for q, k, v (tf32-rounded out).
// ---------------------------------------------------------------------------
__global__ void dw3_kernel(const float* __restrict__ x,
                           const float* __restrict__ wq, const float* __restrict__ bq,
                           const float* __restrict__ wk, const float* __restrict__ bk,
                           const float* __restrict__ wv, const float* __restrict__ bv)
{
    const int b   = blockIdx.y;
    const int c0  = blockIdx.x * 128;
    const int tid = threadIdx.x;            // 256 threads

    __shared__ float sx[64][128];
    const float* xb = x + (size_t)b * NTOK * CDIM;

    #pragma unroll
    for (int i = tid; i < 64 * 128; i += 256) {
        int n = i >> 7, c = i & 127;
        sx[n][c] = xb[n * CDIM + c0 + c];
    }
    __syncthreads();

    const int cl   = tid & 127;
    const int c    = c0 + cl;
    const int half = tid >> 7;

    float wqr[9], wkr[9], wvr[9];
    #pragma unroll
    for (int j = 0; j < 9; ++j) {
        wqr[j] = wq[c * 9 + j];
        wkr[j] = wk[c * 9 + j];
        wvr[j] = wv[c * 9 + j];
    }
    const float bqr = bq[c], bkr = bk[c], bvr = bv[c];

    float* oq = g_scr[0] + (size_t)b * NTOK * CDIM;
    float* ok = g_scr[1] + (size_t)b * NTOK * CDIM;
    float* ov = g_scr[2] + (size_t)b * NTOK * CDIM;

    #pragma unroll 4
    for (int nn = 0; nn < 32; ++nn) {
        int n = half * 32 + nn;
        int l = n >> 3, w = n & 7;
        float aq = bqr, ak = bkr, av = bvr;
        #pragma unroll
        for (int dl = -1; dl <= 1; ++dl) {
            #pragma unroll
            for (int dw = -1; dw <= 1; ++dw) {
                int ll = l + dl, ww = w + dw;
                if (ll < 0 || ll > 7 || ww < 0 || ww > 7) continue;
                float xv = sx[ll * 8 + ww][cl];
                int j = (dl + 1) * 3 + (dw + 1);
                aq += xv * wqr[j];
                ak += xv * wkr[j];
                av += xv * wvr[j];
            }
        }
        int idx = n * CDIM + c;
        oq[idx] = tf32r(fmaxf(aq, 0.0f));
        ok[idx] = tf32r(fmaxf(ak, 0.0f));
        ov[idx] = tf32r(fmaxf(av, 0.0f));
    }
}

// ---------------------------------------------------------------------------
// mma.sync tf32 GEMM body: C[65536,512] = A @ W^T + bias
// CTA 128x128, 256 threads = 8 warps (4x2), warp tile 32x64.
// K-chunk 16, double-buffered smem filled via cp.async.cg (no prefetch regs).
// Rows padded to 20 floats -> conflict-free quad fragment loads.
// ---------------------------------------------------------------------------
#define PAD 20

__device__ __forceinline__ void mma_tf32(float* d, const float* a, const float* b)
{
    asm volatile(
        "mma.sync.aligned.m16n8k8.row.col.f32.tf32.tf32.f32 "
        "{%0,%1,%2,%3}, {%4,%5,%6,%7}, {%8,%9}, {%0,%1,%2,%3};"
        : "+f"(d[0]), "+f"(d[1]), "+f"(d[2]), "+f"(d[3])
        : "r"(__float_as_uint(a[0])), "r"(__float_as_uint(a[1])),
          "r"(__float_as_uint(a[2])), "r"(__float_as_uint(a[3])),
          "r"(__float_as_uint(b[0])), "r"(__float_as_uint(b[1])));
}

__device__ __forceinline__ void cp16(uint32_t dst, const float* src)
{
    asm volatile("cp.async.cg.shared.global [%0], [%1], 16;"
                 :: "r"(dst), "l"(src) : "memory");
}

__device__ __forceinline__ void gemm_body(const float* __restrict__ A,
                                          const float* __restrict__ W,
                                          const float* __restrict__ bias,
                                          float* __restrict__ C)
{
    __shared__ float As[2][128][PAD];
    __shared__ float Bs[2][128][PAD];

    const int tid  = threadIdx.x;
    const int wid  = tid >> 5;
    const int lane = tid & 31;
    const int wm   = wid & 3;        // warp m index (0..3) -> 32 rows each
    const int wn   = wid >> 2;       // warp n index (0..1) -> 64 cols each
    const int m0 = blockIdx.y * 128;
    const int n0 = blockIdx.x * 128;

    const int lrow = tid >> 2;       // 0..63
    const int lc4  = tid & 3;        // float4 index within 16-float row

    const int qrow = lane >> 2;      // 0..7
    const int qcol = lane & 3;       // 0..3

    const uint32_t sA = (uint32_t)__cvta_generic_to_shared(&As[0][0][0]);
    const uint32_t sB = (uint32_t)__cvta_generic_to_shared(&Bs[0][0][0]);

    float acc[2][8][4];
    #pragma unroll
    for (int i = 0; i < 2; ++i)
        #pragma unroll
        for (int j = 0; j < 8; ++j)
            #pragma unroll
            for (int r = 0; r < 4; ++r) acc[i][j][r] = 0.0f;

    const float* Ap = A + (size_t)(m0 + lrow) * 512 + lc4 * 4;
    const float* Bp = W + (size_t)(n0 + lrow) * 512 + lc4 * 4;

    // prologue: stage 0
    {
        #pragma unroll
        for (int r = 0; r < 2; ++r) {
            uint32_t off = (uint32_t)(((lrow + r * 64) * PAD + lc4 * 4) * 4);
            cp16(sA + off, Ap + (size_t)(r * 64) * 512);
            cp16(sB + off, Bp + (size_t)(r * 64) * 512);
        }
        asm volatile("cp.async.commit_group;" ::: "memory");
    }

    #pragma unroll 1
    for (int ch = 0; ch < 32; ++ch) {
        const int s = ch & 1;
        if (ch < 31) {
            const int ns = (ch + 1) & 1;
            const int kb = (ch + 1) * 16;
            #pragma unroll
            for (int r = 0; r < 2; ++r) {
                uint32_t off = (uint32_t)(((ns * 128 + lrow + r * 64) * PAD + lc4 * 4) * 4);
                cp16(sA + off, Ap + (size_t)(r * 64) * 512 + kb);
                cp16(sB + off, Bp + (size_t)(r * 64) * 512 + kb);
            }
        }
        asm volatile("cp.async.commit_group;" ::: "memory");
        asm volatile("cp.async.wait_group 1;" ::: "memory");
        __syncthreads();

        #pragma unroll
        for (int k8 = 0; k8 < 16; k8 += 8) {
            float a[2][4];
            #pragma unroll
            for (int mi = 0; mi < 2; ++mi) {
                const int mr = wm * 32 + mi * 16 + qrow;
                a[mi][0] = As[s][mr][k8 + qcol];
                a[mi][1] = As[s][mr + 8][k8 + qcol];
                a[mi][2] = As[s][mr][k8 + qcol + 4];
                a[mi][3] = As[s][mr + 8][k8 + qcol + 4];
            }
            float b[8][2];
            #pragma unroll
            for (int ni = 0; ni < 8; ++ni) {
                const int nc = wn * 64 + ni * 8 + qrow;
                b[ni][0] = Bs[s][nc][k8 + qcol];
                b[ni][1] = Bs[s][nc][k8 + qcol + 4];
            }
            #pragma unroll
            for (int mi = 0; mi < 2; ++mi)
                #pragma unroll
                for (int ni = 0; ni < 8; ++ni)
                    mma_tf32(acc[mi][ni], a[mi], b[ni]);
        }
        __syncthreads();
    }

    // Epilogue: add bias, float2 stores
    #pragma unroll
    for (int ni = 0; ni < 8; ++ni) {
        const int n = n0 + wn * 64 + ni * 8 + (qcol << 1);
        const float2 bv = *(const float2*)(bias + n);
        #pragma unroll
        for (int mi = 0; mi < 2; ++mi) {
            const int m = m0 + wm * 32 + mi * 16 + qrow;
            float2 o0, o1;
            o0.x = acc[mi][ni][0] + bv.x; o0.y = acc[mi][ni][1] + bv.y;
            o1.x = acc[mi][ni][2] + bv.x; o1.y = acc[mi][ni][3] + bv.y;
            *(float2*)(C + (size_t)m * 512 + n) = o0;
            *(float2*)(C + (size_t)(m + 8) * 512 + n) = o1;
        }
    }
}

// QKV: grid.z selects slot (0,1,2) -> writes slots (3,4,5)
__global__ void __launch_bounds__(256, 2)
gemm_qkv(const float* __restrict__ bq, const float* __restrict__ bk,
         const float* __restrict__ bv)
{
    const int z = blockIdx.z;
    const float* bias = (z == 0) ? bq : (z == 1) ? bk : bv;
    gemm_body(g_scr[z], g_w[z], bias, g_scr[3 + z]);
}

__global__ void __launch_bounds__(256, 2)
gemm_proj(const float* __restrict__ bias, float* __restrict__ C)
{
    gemm_body(g_scr[0], g_w[3], bias, C);
}

// ---------------------------------------------------------------------------
// Kernel 3: attention per (b, h). float4 smem traffic; output tf32-rounded.
// ---------------------------------------------------------------------------
__global__ void __launch_bounds__(64)
attn_kernel(const float* __restrict__ pos, const float* __restrict__ mask)
{
    const int bh = blockIdx.x;
    const int b = bh >> 4;
    const int h = bh & 15;
    const int n = threadIdx.x;   // 0..63

    __shared__ float4 ks4[64][8];
    __shared__ float4 vs4[64][8];
    __shared__ float4 qs4[64][9];   // pad col -> conflict-free own-row reads

    const float* Q  = g_scr[3];
    const float* Kt = g_scr[4];
    const float* V  = g_scr[5];
    const size_t base = (size_t)b * 64 * 512 + h * 32;

    #pragma unroll
    for (int i = n; i < 64 * 8; i += 64) {
        int m = i >> 3, j = i & 7;
        ks4[m][j] = *(const float4*)(Kt + base + (size_t)m * 512 + j * 4);
        vs4[m][j] = *(const float4*)(V + base + (size_t)m * 512 + j * 4);
        qs4[m][j] = *(const float4*)(Q + base + (size_t)m * 512 + j * 4);
    }
    __syncthreads();

    const float scale = 0.17677669529663687f; // 1/sqrt(32)
    float qr[32];
    #pragma unroll
    for (int j = 0; j < 8; ++j) {
        float4 t = qs4[n][j];
        qr[j*4+0] = t.x * scale; qr[j*4+1] = t.y * scale;
        qr[j*4+2] = t.z * scale; qr[j*4+3] = t.w * scale;
    }

    const float* pr = pos + n * 64;
    const float* mr = mask + ((size_t)b * 64 + n) * 64;

    float s[64];
    float mx = -1e30f;
    #pragma unroll
    for (int m = 0; m < 64; ++m) {
        float acc = 0.0f;
        #pragma unroll
        for (int j = 0; j < 8; ++j) {
            float4 kv = ks4[m][j];
            acc += qr[j*4+0] * kv.x + qr[j*4+1] * kv.y
                 + qr[j*4+2] * kv.z + qr[j*4+3] * kv.w;
        }
        acc += pr[m] + mr[m];
        s[m] = acc;
        mx = fmaxf(mx, acc);
    }
    float sum = 0.0f;
    #pragma unroll
    for (int m = 0; m < 64; ++m) {
        s[m] = __expf(s[m] - mx);
        sum += s[m];
    }
    const float inv = 1.0f / sum;

    float o[32];
    #pragma unroll
    for (int d = 0; d < 32; ++d) o[d] = 0.0f;
    #pragma unroll
    for (int m = 0; m < 64; ++m) {
        const float p = s[m];
        #pragma unroll
        for (int j = 0; j < 8; ++j) {
            float4 vv = vs4[m][j];
            o[j*4+0] += p * vv.x; o[j*4+1] += p * vv.y;
            o[j*4+2] += p * vv.z; o[j*4+3] += p * vv.w;
        }
    }

    float* Op = g_scr[0] + base + (size_t)n * 512;
    #pragma unroll
    for (int d = 0; d < 32; d += 4) {
        float4 w;
        w.x = tf32r(o[d + 0] * inv); w.y = tf32r(o[d + 1] * inv);
        w.z = tf32r(o[d + 2] * inv); w.w = tf32r(o[d + 3] * inv);
        *(float4*)(Op + d) = w;
    }
}

// ---------------------------------------------------------------------------
// Launch
// ---------------------------------------------------------------------------
extern "C" void kernel_launch(void* const* d_in, const int* in_sizes, int n_in,
                              void* d_out, int out_size)
{
    const float* x      = (const float*)d_in[0];
    const float* mask   = (const float*)d_in[1];
    const float* dwq_w  = (const float*)d_in[2];
    const float* dwq_b  = (const float*)d_in[3];
    const float* pwq_w  = (const float*)d_in[4];
    const float* pwq_b  = (const float*)d_in[5];
    const float* dwk_w  = (const float*)d_in[6];
    const float* dwk_b  = (const float*)d_in[7];
    const float* pwk_w  = (const float*)d_in[8];
    const float* pwk_b  = (const float*)d_in[9];
    const float* dwv_w  = (const float*)d_in[10];
    const float* dwv_b  = (const float*)d_in[11];
    const float* pwv_w  = (const float*)d_in[12];
    const float* pwv_b  = (const float*)d_in[13];
    const float* pos    = (const float*)d_in[14];
    const float* proj_w = (const float*)d_in[15];
    const float* proj_b = (const float*)d_in[16];

    // 0. round weights to tf32
    prep_w<<<4096, 256>>>(pwq_w, pwk_w, pwv_w, proj_w);

    // 1. depthwise 3x3 + ReLU -> slots 0,1,2
    dim3 gdw(4, BW);
    dw3_kernel<<<gdw, 256>>>(x, dwq_w, dwq_b, dwk_w, dwk_b, dwv_w, dwv_b);

    // 2. pointwise GEMMs (one launch, z = q/k/v) -> slots 3,4,5
    dim3 gqkv(4, 512, 3);
    gemm_qkv<<<gqkv, 256>>>(pwq_b, pwk_b, pwv_b);

    // 3. attention -> slot 0
    attn_kernel<<<BW * HEADS, 64>>>(pos, mask);

    // 4. output projection -> d_out
    dim3 gg(4, 512);
    gemm_proj<<<gg, 256>>>(proj_b, (float*)d_out);
}

// round 6
// speedup vs baseline: 3.3382x; 1.4306x over previous
#include <cuda_runtime.h>
#include <math.h>
#include <stdint.h>

// Problem constants
#define BW    1024          // windows (batch)
#define NTOK  64            // tokens per window (8x8)
#define CDIM  512           // channels
#define HEADS 16
#define HD    32            // head dim
#define BNC   (BW*NTOK*CDIM)

// Scratch slots:
// slot 0: dwq -> later attention output
// slot 1: dwk   slot 2: dwv
// slot 3: q     slot 4: k     slot 5: v
__device__ float g_scr[6][BNC];
// tf32-rounded weights: 0=pwq, 1=pwk, 2=pwv, 3=proj
__device__ float g_w[4][CDIM*CDIM];

__device__ __forceinline__ float tf32r(float x) {
    uint32_t r;
    asm("cvt.rna.tf32.f32 %0, %1;" : "=r"(r) : "f"(x));
    return __uint_as_float(r);
}

// ---------------------------------------------------------------------------
// Weight prep: round 4x [512,512] fp32 weights to tf32.
// ---------------------------------------------------------------------------
__global__ void prep_w(const float* __restrict__ w0, const float* __restrict__ w1,
                       const float* __restrict__ w2, const float* __restrict__ w3)
{
    int idx = blockIdx.x * 256 + threadIdx.x;
    int w = idx >> 18, j = idx & 262143;
    const float* s = (w == 0) ? w0 : (w == 1) ? w1 : (w == 2) ? w2 : w3;
    g_w[w][j] = tf32r(s[j]);
}

// ---------------------------------------------------------------------------
// Kernel 1: fused depthwise 3x3 (+bias, ReLU) for q, k, v (tf32-rounded out).
// ---------------------------------------------------------------------------
__global__ void dw3_kernel(const float* __restrict__ x,
                           const float* __restrict__ wq, const float* __restrict__ bq,
                           const float* __restrict__ wk, const float* __restrict__ bk,
                           const float* __restrict__ wv, const float* __restrict__ bv)
{
    const int b   = blockIdx.y;
    const int c0  = blockIdx.x * 128;
    const int tid = threadIdx.x;            // 256 threads

    __shared__ float sx[64][128];
    const float* xb = x + (size_t)b * NTOK * CDIM;

    #pragma unroll
    for (int i = tid; i < 64 * 128; i += 256) {
        int n = i >> 7, c = i & 127;
        sx[n][c] = xb[n * CDIM + c0 + c];
    }
    __syncthreads();

    const int cl   = tid & 127;
    const int c    = c0 + cl;
    const int half = tid >> 7;

    float wqr[9], wkr[9], wvr[9];
    #pragma unroll
    for (int j = 0; j < 9; ++j) {
        wqr[j] = wq[c * 9 + j];
        wkr[j] = wk[c * 9 + j];
        wvr[j] = wv[c * 9 + j];
    }
    const float bqr = bq[c], bkr = bk[c], bvr = bv[c];

    float* oq = g_scr[0] + (size_t)b * NTOK * CDIM;
    float* ok = g_scr[1] + (size_t)b * NTOK * CDIM;
    float* ov = g_scr[2] + (size_t)b * NTOK * CDIM;

    #pragma unroll 4
    for (int nn = 0; nn < 32; ++nn) {
        int n = half * 32 + nn;
        int l = n >> 3, w = n & 7;
        float aq = bqr, ak = bkr, av = bvr;
        #pragma unroll
        for (int dl = -1; dl <= 1; ++dl) {
            #pragma unroll
            for (int dw = -1; dw <= 1; ++dw) {
                int ll = l + dl, ww = w + dw;
                if (ll < 0 || ll > 7 || ww < 0 || ww > 7) continue;
                float xv = sx[ll * 8 + ww][cl];
                int j = (dl + 1) * 3 + (dw + 1);
                aq += xv * wqr[j];
                ak += xv * wkr[j];
                av += xv * wvr[j];
            }
        }
        int idx = n * CDIM + c;
        oq[idx] = tf32r(fmaxf(aq, 0.0f));
        ok[idx] = tf32r(fmaxf(ak, 0.0f));
        ov[idx] = tf32r(fmaxf(av, 0.0f));
    }
}

// ---------------------------------------------------------------------------
// mma.sync helpers
// ---------------------------------------------------------------------------
__device__ __forceinline__ void mma_tf32(float* d, const float* a, const float* b)
{
    asm volatile(
        "mma.sync.aligned.m16n8k8.row.col.f32.tf32.tf32.f32 "
        "{%0,%1,%2,%3}, {%4,%5,%6,%7}, {%8,%9}, {%0,%1,%2,%3};"
        : "+f"(d[0]), "+f"(d[1]), "+f"(d[2]), "+f"(d[3])
        : "r"(__float_as_uint(a[0])), "r"(__float_as_uint(a[1])),
          "r"(__float_as_uint(a[2])), "r"(__float_as_uint(a[3])),
          "r"(__float_as_uint(b[0])), "r"(__float_as_uint(b[1])));
}

__device__ __forceinline__ void cp16(uint32_t dst, const float* src)
{
    asm volatile("cp.async.cg.shared.global [%0], [%1], 16;"
                 :: "r"(dst), "l"(src) : "memory");
}

// ---------------------------------------------------------------------------
// mma.sync tf32 GEMM body: C[65536,512] = A @ W^T + bias
// CTA 128x128, 256 threads = 8 warps (4x2), warp tile 32x64.
// K-chunk 16, double-buffered smem via cp.async.cg, rows padded to 20 floats.
// ---------------------------------------------------------------------------
#define PAD 20

__device__ __forceinline__ void gemm_body(const float* __restrict__ A,
                                          const float* __restrict__ W,
                                          const float* __restrict__ bias,
                                          float* __restrict__ C)
{
    __shared__ float As[2][128][PAD];
    __shared__ float Bs[2][128][PAD];

    const int tid  = threadIdx.x;
    const int wid  = tid >> 5;
    const int lane = tid & 31;
    const int wm   = wid & 3;
    const int wn   = wid >> 2;
    const int m0 = blockIdx.y * 128;
    const int n0 = blockIdx.x * 128;

    const int lrow = tid >> 2;
    const int lc4  = tid & 3;

    const int qrow = lane >> 2;
    const int qcol = lane & 3;

    const uint32_t sA = (uint32_t)__cvta_generic_to_shared(&As[0][0][0]);
    const uint32_t sB = (uint32_t)__cvta_generic_to_shared(&Bs[0][0][0]);

    float acc[2][8][4];
    #pragma unroll
    for (int i = 0; i < 2; ++i)
        #pragma unroll
        for (int j = 0; j < 8; ++j)
            #pragma unroll
            for (int r = 0; r < 4; ++r) acc[i][j][r] = 0.0f;

    const float* Ap = A + (size_t)(m0 + lrow) * 512 + lc4 * 4;
    const float* Bp = W + (size_t)(n0 + lrow) * 512 + lc4 * 4;

    {
        #pragma unroll
        for (int r = 0; r < 2; ++r) {
            uint32_t off = (uint32_t)(((lrow + r * 64) * PAD + lc4 * 4) * 4);
            cp16(sA + off, Ap + (size_t)(r * 64) * 512);
            cp16(sB + off, Bp + (size_t)(r * 64) * 512);
        }
        asm volatile("cp.async.commit_group;" ::: "memory");
    }

    #pragma unroll 1
    for (int ch = 0; ch < 32; ++ch) {
        const int s = ch & 1;
        if (ch < 31) {
            const int ns = (ch + 1) & 1;
            const int kb = (ch + 1) * 16;
            #pragma unroll
            for (int r = 0; r < 2; ++r) {
                uint32_t off = (uint32_t)(((ns * 128 + lrow + r * 64) * PAD + lc4 * 4) * 4);
                cp16(sA + off, Ap + (size_t)(r * 64) * 512 + kb);
                cp16(sB + off, Bp + (size_t)(r * 64) * 512 + kb);
            }
        }
        asm volatile("cp.async.commit_group;" ::: "memory");
        asm volatile("cp.async.wait_group 1;" ::: "memory");
        __syncthreads();

        #pragma unroll
        for (int k8 = 0; k8 < 16; k8 += 8) {
            float a[2][4];
            #pragma unroll
            for (int mi = 0; mi < 2; ++mi) {
                const int mr = wm * 32 + mi * 16 + qrow;
                a[mi][0] = As[s][mr][k8 + qcol];
                a[mi][1] = As[s][mr + 8][k8 + qcol];
                a[mi][2] = As[s][mr][k8 + qcol + 4];
                a[mi][3] = As[s][mr + 8][k8 + qcol + 4];
            }
            float b[8][2];
            #pragma unroll
            for (int ni = 0; ni < 8; ++ni) {
                const int nc = wn * 64 + ni * 8 + qrow;
                b[ni][0] = Bs[s][nc][k8 + qcol];
                b[ni][1] = Bs[s][nc][k8 + qcol + 4];
            }
            #pragma unroll
            for (int mi = 0; mi < 2; ++mi)
                #pragma unroll
                for (int ni = 0; ni < 8; ++ni)
                    mma_tf32(acc[mi][ni], a[mi], b[ni]);
        }
        __syncthreads();
    }

    #pragma unroll
    for (int ni = 0; ni < 8; ++ni) {
        const int n = n0 + wn * 64 + ni * 8 + (qcol << 1);
        const float2 bv = *(const float2*)(bias + n);
        #pragma unroll
        for (int mi = 0; mi < 2; ++mi) {
            const int m = m0 + wm * 32 + mi * 16 + qrow;
            float2 o0, o1;
            o0.x = acc[mi][ni][0] + bv.x; o0.y = acc[mi][ni][1] + bv.y;
            o1.x = acc[mi][ni][2] + bv.x; o1.y = acc[mi][ni][3] + bv.y;
            *(float2*)(C + (size_t)m * 512 + n) = o0;
            *(float2*)(C + (size_t)(m + 8) * 512 + n) = o1;
        }
    }
}

// QKV: grid.z selects slot (0,1,2) -> writes slots (3,4,5)
__global__ void __launch_bounds__(256, 2)
gemm_qkv(const float* __restrict__ bq, const float* __restrict__ bk,
         const float* __restrict__ bv)
{
    const int z = blockIdx.z;
    const float* bias = (z == 0) ? bq : (z == 1) ? bk : bv;
    gemm_body(g_scr[z], g_w[z], bias, g_scr[3 + z]);
}

__global__ void __launch_bounds__(256, 2)
gemm_proj(const float* __restrict__ bias, float* __restrict__ C)
{
    gemm_body(g_scr[0], g_w[3], bias, C);
}

// ---------------------------------------------------------------------------
// Kernel 3: tensor-core attention. One block (128 thr, 4 warps) per (b,h).
// Warp w owns S/O rows [16w,16w+16): S = Q*K^T via mma (8 n-tiles x 4 k-tiles),
// fragment softmax (quad shfl reductions), P through padded smem, O = P*V via
// mma (4 n-tiles x 8 k-tiles). All mma operands tf32-rounded.
// ---------------------------------------------------------------------------
__global__ void __launch_bounds__(128)
attn_mma(const float* __restrict__ pos, const float* __restrict__ mask)
{
    const int bh = blockIdx.x;
    const int b = bh >> 4;
    const int h = bh & 15;
    const int tid  = threadIdx.x;
    const int wid  = tid >> 5;
    const int lane = tid & 31;
    const int qrow = lane >> 2;
    const int qcol = lane & 3;

    __shared__ float Qs[64][36];       // (4r+c) mod 32 -> conflict-free frags
    __shared__ float Ks[64][36];
    __shared__ float Vt[32][68];       // V transposed [dim][token]
    __shared__ float Ps[4][16][68];    // per-warp P tile

    const float* Q  = g_scr[3];
    const float* Kt = g_scr[4];
    const float* V  = g_scr[5];
    const size_t base = (size_t)b * 64 * 512 + h * 32;

    const float scale = 0.17677669529663687f; // 1/sqrt(32)

    // Stage Q (scaled), K, V^T into smem, tf32-rounded.
    #pragma unroll
    for (int i = tid; i < 512; i += 128) {
        const int t = i >> 3, j = i & 7;          // token, float4 group
        const size_t g = base + (size_t)t * 512 + j * 4;
        float4 qv = *(const float4*)(Q + g);
        float4 kv = *(const float4*)(Kt + g);
        float4 vv = *(const float4*)(V + g);
        float4 qo;
        qo.x = tf32r(qv.x * scale); qo.y = tf32r(qv.y * scale);
        qo.z = tf32r(qv.z * scale); qo.w = tf32r(qv.w * scale);
        *(float4*)&Qs[t][j * 4] = qo;
        float4 ko;
        ko.x = tf32r(kv.x); ko.y = tf32r(kv.y);
        ko.z = tf32r(kv.z); ko.w = tf32r(kv.w);
        *(float4*)&Ks[t][j * 4] = ko;
        Vt[j * 4 + 0][t] = tf32r(vv.x);
        Vt[j * 4 + 1][t] = tf32r(vv.y);
        Vt[j * 4 + 2][t] = tf32r(vv.z);
        Vt[j * 4 + 3][t] = tf32r(vv.w);
    }
    __syncthreads();

    // S = Q K^T  (warp rows m0..m0+15)
    const int m0 = wid * 16;
    float acc[8][4];
    #pragma unroll
    for (int nt = 0; nt < 8; ++nt)
        #pragma unroll
        for (int r = 0; r < 4; ++r) acc[nt][r] = 0.0f;

    #pragma unroll
    for (int kt = 0; kt < 4; ++kt) {
        const int k8 = kt * 8;
        float a[4];
        a[0] = Qs[m0 + qrow][k8 + qcol];
        a[1] = Qs[m0 + qrow + 8][k8 + qcol];
        a[2] = Qs[m0 + qrow][k8 + qcol + 4];
        a[3] = Qs[m0 + qrow + 8][k8 + qcol + 4];
        #pragma unroll
        for (int nt = 0; nt < 8; ++nt) {
            float b2[2];
            b2[0] = Ks[nt * 8 + qrow][k8 + qcol];
            b2[1] = Ks[nt * 8 + qrow][k8 + qcol + 4];
            mma_tf32(acc[nt], a, b2);
        }
    }

    // pos + mask, then fragment softmax (rows r0, r1 owned by this quad)
    const int r0 = m0 + qrow, r1 = r0 + 8;
    const int cb = qcol * 2;
    float mx0 = -1e30f, mx1 = -1e30f;
    #pragma unroll
    for (int nt = 0; nt < 8; ++nt) {
        const int col = nt * 8 + cb;
        const float2 p0 = *(const float2*)(pos + r0 * 64 + col);
        const float2 p1 = *(const float2*)(pos + r1 * 64 + col);
        const float2 g0 = *(const float2*)(mask + ((size_t)b * 64 + r0) * 64 + col);
        const float2 g1 = *(const float2*)(mask + ((size_t)b * 64 + r1) * 64 + col);
        acc[nt][0] += p0.x + g0.x;
        acc[nt][1] += p0.y + g0.y;
        acc[nt][2] += p1.x + g1.x;
        acc[nt][3] += p1.y + g1.y;
        mx0 = fmaxf(mx0, fmaxf(acc[nt][0], acc[nt][1]));
        mx1 = fmaxf(mx1, fmaxf(acc[nt][2], acc[nt][3]));
    }
    mx0 = fmaxf(mx0, __shfl_xor_sync(0xffffffffu, mx0, 1));
    mx0 = fmaxf(mx0, __shfl_xor_sync(0xffffffffu, mx0, 2));
    mx1 = fmaxf(mx1, __shfl_xor_sync(0xffffffffu, mx1, 1));
    mx1 = fmaxf(mx1, __shfl_xor_sync(0xffffffffu, mx1, 2));

    float s0 = 0.0f, s1 = 0.0f;
    #pragma unroll
    for (int nt = 0; nt < 8; ++nt) {
        acc[nt][0] = __expf(acc[nt][0] - mx0);
        acc[nt][1] = __expf(acc[nt][1] - mx0);
        acc[nt][2] = __expf(acc[nt][2] - mx1);
        acc[nt][3] = __expf(acc[nt][3] - mx1);
        s0 += acc[nt][0] + acc[nt][1];
        s1 += acc[nt][2] + acc[nt][3];
    }
    s0 += __shfl_xor_sync(0xffffffffu, s0, 1);
    s0 += __shfl_xor_sync(0xffffffffu, s0, 2);
    s1 += __shfl_xor_sync(0xffffffffu, s1, 1);
    s1 += __shfl_xor_sync(0xffffffffu, s1, 2);
    const float inv0 = 1.0f / s0;
    const float inv1 = 1.0f / s1;

    // store P (tf32-rounded, unnormalized) to per-warp smem tile
    float (*Pw)[68] = Ps[wid];
    #pragma unroll
    for (int nt = 0; nt < 8; ++nt) {
        const int col = nt * 8 + cb;
        *(float2*)&Pw[qrow][col]     = make_float2(tf32r(acc[nt][0]), tf32r(acc[nt][1]));
        *(float2*)&Pw[qrow + 8][col] = make_float2(tf32r(acc[nt][2]), tf32r(acc[nt][3]));
    }
    __syncwarp();

    // O = P V   (K = 64 tokens, N = 32 dims)
    float oacc[4][4];
    #pragma unroll
    for (int nt = 0; nt < 4; ++nt)
        #pragma unroll
        for (int r = 0; r < 4; ++r) oacc[nt][r] = 0.0f;

    #pragma unroll
    for (int kt = 0; kt < 8; ++kt) {
        const int k8 = kt * 8;
        float a[4];
        a[0] = Pw[qrow][k8 + qcol];
        a[1] = Pw[qrow + 8][k8 + qcol];
        a[2] = Pw[qrow][k8 + qcol + 4];
        a[3] = Pw[qrow + 8][k8 + qcol + 4];
        #pragma unroll
        for (int nt = 0; nt < 4; ++nt) {
            float b2[2];
            b2[0] = Vt[nt * 8 + qrow][k8 + qcol];
            b2[1] = Vt[nt * 8 + qrow][k8 + qcol + 4];
            mma_tf32(oacc[nt], a, b2);
        }
    }

    // epilogue: normalize, round, store to slot 0 at [b][token][h*32+dim]
    float* O = g_scr[0] + base;
    #pragma unroll
    for (int nt = 0; nt < 4; ++nt) {
        const int col = nt * 8 + cb;
        float2 w0, w1;
        w0.x = tf32r(oacc[nt][0] * inv0); w0.y = tf32r(oacc[nt][1] * inv0);
        w1.x = tf32r(oacc[nt][2] * inv1); w1.y = tf32r(oacc[nt][3] * inv1);
        *(float2*)(O + (size_t)r0 * 512 + col) = w0;
        *(float2*)(O + (size_t)r1 * 512 + col) = w1;
    }
}

// ---------------------------------------------------------------------------
// Launch
// ---------------------------------------------------------------------------
extern "C" void kernel_launch(void* const* d_in, const int* in_sizes, int n_in,
                              void* d_out, int out_size)
{
    const float* x      = (const float*)d_in[0];
    const float* mask   = (const float*)d_in[1];
    const float* dwq_w  = (const float*)d_in[2];
    const float* dwq_b  = (const float*)d_in[3];
    const float* pwq_w  = (const float*)d_in[4];
    const float* pwq_b  = (const float*)d_in[5];
    const float* dwk_w  = (const float*)d_in[6];
    const float* dwk_b  = (const float*)d_in[7];
    const float* pwk_w  = (const float*)d_in[8];
    const float* pwk_b  = (const float*)d_in[9];
    const float* dwv_w  = (const float*)d_in[10];
    const float* dwv_b  = (const float*)d_in[11];
    const float* pwv_w  = (const float*)d_in[12];
    const float* pwv_b  = (const float*)d_in[13];
    const float* pos    = (const float*)d_in[14];
    const float* proj_w = (const float*)d_in[15];
    const float* proj_b = (const float*)d_in[16];

    // 0. round weights to tf32
    prep_w<<<4096, 256>>>(pwq_w, pwk_w, pwv_w, proj_w);

    // 1. depthwise 3x3 + ReLU -> slots 0,1,2
    dim3 gdw(4, BW);
    dw3_kernel<<<gdw, 256>>>(x, dwq_w, dwq_b, dwk_w, dwk_b, dwv_w, dwv_b);

    // 2. pointwise GEMMs (one launch, z = q/k/v) -> slots 3,4,5
    dim3 gqkv(4, 512, 3);
    gemm_qkv<<<gqkv, 256>>>(pwq_b, pwk_b, pwv_b);

    // 3. tensor-core attention -> slot 0
    attn_mma<<<BW * HEADS, 128>>>(pos, mask);

    // 4. output projection -> d_out
    dim3 gg(4, 512);
    gemm_proj<<<gg, 256>>>(proj_b, (float*)d_out);
}

// round 7
// speedup vs baseline: 3.4625x; 1.0372x over previous
#include <cuda_runtime.h>
#include <math.h>
#include <stdint.h>

// Problem constants
#define BW    1024          // windows (batch)
#define NTOK  64            // tokens per window (8x8)
#define CDIM  512           // channels
#define HEADS 16
#define HD    32            // head dim
#define BNC   (BW*NTOK*CDIM)

// Scratch slots:
// slot 0: dwq -> later attention output
// slot 1: dwk   slot 2: dwv
// slot 3: q     slot 4: k     slot 5: v
__device__ float g_scr[6][BNC];
// tf32-rounded weights: 0=pwq, 1=pwk, 2=pwv, 3=proj
__device__ float g_w[4][CDIM*CDIM];

__device__ __forceinline__ float tf32r(float x) {
    uint32_t r;
    asm("cvt.rna.tf32.f32 %0, %1;" : "=r"(r) : "f"(x));
    return __uint_as_float(r);
}

// ---------------------------------------------------------------------------
// Weight prep: round 4x [512,512] fp32 weights to tf32.
// ---------------------------------------------------------------------------
__global__ void prep_w(const float* __restrict__ w0, const float* __restrict__ w1,
                       const float* __restrict__ w2, const float* __restrict__ w3)
{
    int idx = blockIdx.x * 256 + threadIdx.x;
    int w = idx >> 18, j = idx & 262143;
    const float* s = (w == 0) ? w0 : (w == 1) ? w1 : (w == 2) ? w2 : w3;
    g_w[w][j] = tf32r(s[j]);
}

// ---------------------------------------------------------------------------
// Kernel 1: fused depthwise 3x3 (+bias, ReLU) for q, k, v (tf32-rounded out).
// ---------------------------------------------------------------------------
__global__ void dw3_kernel(const float* __restrict__ x,
                           const float* __restrict__ wq, const float* __restrict__ bq,
                           const float* __restrict__ wk, const float* __restrict__ bk,
                           const float* __restrict__ wv, const float* __restrict__ bv)
{
    const int b   = blockIdx.y;
    const int c0  = blockIdx.x * 128;
    const int tid = threadIdx.x;            // 256 threads

    __shared__ float sx[64][128];
    const float* xb = x + (size_t)b * NTOK * CDIM;

    #pragma unroll
    for (int i = tid; i < 64 * 128; i += 256) {
        int n = i >> 7, c = i & 127;
        sx[n][c] = xb[n * CDIM + c0 + c];
    }
    __syncthreads();

    const int cl   = tid & 127;
    const int c    = c0 + cl;
    const int half = tid >> 7;

    float wqr[9], wkr[9], wvr[9];
    #pragma unroll
    for (int j = 0; j < 9; ++j) {
        wqr[j] = wq[c * 9 + j];
        wkr[j] = wk[c * 9 + j];
        wvr[j] = wv[c * 9 + j];
    }
    const float bqr = bq[c], bkr = bk[c], bvr = bv[c];

    float* oq = g_scr[0] + (size_t)b * NTOK * CDIM;
    float* ok = g_scr[1] + (size_t)b * NTOK * CDIM;
    float* ov = g_scr[2] + (size_t)b * NTOK * CDIM;

    #pragma unroll 4
    for (int nn = 0; nn < 32; ++nn) {
        int n = half * 32 + nn;
        int l = n >> 3, w = n & 7;
        float aq = bqr, ak = bkr, av = bvr;
        #pragma unroll
        for (int dl = -1; dl <= 1; ++dl) {
            #pragma unroll
            for (int dw = -1; dw <= 1; ++dw) {
                int ll = l + dl, ww = w + dw;
                if (ll < 0 || ll > 7 || ww < 0 || ww > 7) continue;
                float xv = sx[ll * 8 + ww][cl];
                int j = (dl + 1) * 3 + (dw + 1);
                aq += xv * wqr[j];
                ak += xv * wkr[j];
                av += xv * wvr[j];
            }
        }
        int idx = n * CDIM + c;
        oq[idx] = tf32r(fmaxf(aq, 0.0f));
        ok[idx] = tf32r(fmaxf(ak, 0.0f));
        ov[idx] = tf32r(fmaxf(av, 0.0f));
    }
}

// ---------------------------------------------------------------------------
// mma.sync helpers
// ---------------------------------------------------------------------------
__device__ __forceinline__ void mma_tf32(float* d, const float* a, const float* b)
{
    asm volatile(
        "mma.sync.aligned.m16n8k8.row.col.f32.tf32.tf32.f32 "
        "{%0,%1,%2,%3}, {%4,%5,%6,%7}, {%8,%9}, {%0,%1,%2,%3};"
        : "+f"(d[0]), "+f"(d[1]), "+f"(d[2]), "+f"(d[3])
        : "r"(__float_as_uint(a[0])), "r"(__float_as_uint(a[1])),
          "r"(__float_as_uint(a[2])), "r"(__float_as_uint(a[3])),
          "r"(__float_as_uint(b[0])), "r"(__float_as_uint(b[1])));
}

__device__ __forceinline__ void cp16(uint32_t dst, const float* src)
{
    asm volatile("cp.async.cg.shared.global [%0], [%1], 16;"
                 :: "r"(dst), "l"(src) : "memory");
}

// ---------------------------------------------------------------------------
// mma.sync tf32 GEMM body: C[65536,512] = A @ W^T + bias
// CTA 128x128, 128 threads = 4 warps (2x2), warp tile 64x64.
// K-chunk 16, 3-stage cp.async ring (2-chunk prefetch slack), one
// __syncthreads per chunk. Rows padded to 20 floats (conflict-free frags).
// ---------------------------------------------------------------------------
#define PAD 20
#define GSTAGE_F (128 * PAD)                 // floats per stage per matrix
#define GSMEM_BYTES (2 * 3 * GSTAGE_F * 4)   // 61440

__device__ __forceinline__ void gemm_body(const float* __restrict__ A,
                                          const float* __restrict__ W,
                                          const float* __restrict__ bias,
                                          float* __restrict__ C)
{
    extern __shared__ float dsm[];           // [3][128][PAD] A, then B

    const int tid  = threadIdx.x;            // 128 threads
    const int wid  = tid >> 5;
    const int lane = tid & 31;
    const int wm   = wid & 1;                // 2 m-halves of 64
    const int wn   = wid >> 1;               // 2 n-halves of 64
    const int m0 = blockIdx.y * 128;
    const int n0 = blockIdx.x * 128;

    const int lrow = tid >> 2;               // 0..31
    const int lc4  = tid & 3;                // float4 column

    const int qrow = lane >> 2;              // 0..7
    const int qcol = lane & 3;               // 0..3

    const uint32_t sA = (uint32_t)__cvta_generic_to_shared(dsm);
    const uint32_t sB = sA + 3 * GSTAGE_F * 4;

    float acc[4][8][4];
    #pragma unroll
    for (int i = 0; i < 4; ++i)
        #pragma unroll
        for (int j = 0; j < 8; ++j)
            #pragma unroll
            for (int r = 0; r < 4; ++r) acc[i][j][r] = 0.0f;

    const float* Ap = A + (size_t)(m0 + lrow) * 512 + lc4 * 4;
    const float* Bp = W + (size_t)(n0 + lrow) * 512 + lc4 * 4;

    // prologue: stages 0,1
    #pragma unroll
    for (int st = 0; st < 2; ++st) {
        #pragma unroll
        for (int r = 0; r < 4; ++r) {
            uint32_t off = (uint32_t)(((st * 128 + lrow + r * 32) * PAD + lc4 * 4) * 4);
            cp16(sA + off, Ap + (size_t)(r * 32) * 512 + st * 16);
            cp16(sB + off, Bp + (size_t)(r * 32) * 512 + st * 16);
        }
        asm volatile("cp.async.commit_group;" ::: "memory");
    }

    int s = 0, p = 2;
    #pragma unroll 1
    for (int ch = 0; ch < 32; ++ch) {
        asm volatile("cp.async.wait_group 1;" ::: "memory");
        __syncthreads();

        // prefetch stage p = (ch+2)%3 (its last reader finished at ch-1,
        // guaranteed by program order + the barrier above)
        if (ch < 30) {
            const int kb = (ch + 2) * 16;
            #pragma unroll
            for (int r = 0; r < 4; ++r) {
                uint32_t off = (uint32_t)(((p * 128 + lrow + r * 32) * PAD + lc4 * 4) * 4);
                cp16(sA + off, Ap + (size_t)(r * 32) * 512 + kb);
                cp16(sB + off, Bp + (size_t)(r * 32) * 512 + kb);
            }
        }
        asm volatile("cp.async.commit_group;" ::: "memory");

        const float* Ab = dsm + s * GSTAGE_F;
        const float* Bb = dsm + 3 * GSTAGE_F + s * GSTAGE_F;

        #pragma unroll
        for (int k8 = 0; k8 < 16; k8 += 8) {
            float a[4][4];
            #pragma unroll
            for (int mi = 0; mi < 4; ++mi) {
                const int mr = wm * 64 + mi * 16 + qrow;
                a[mi][0] = Ab[mr * PAD + k8 + qcol];
                a[mi][1] = Ab[(mr + 8) * PAD + k8 + qcol];
                a[mi][2] = Ab[mr * PAD + k8 + qcol + 4];
                a[mi][3] = Ab[(mr + 8) * PAD + k8 + qcol + 4];
            }
            float b[8][2];
            #pragma unroll
            for (int ni = 0; ni < 8; ++ni) {
                const int nc = wn * 64 + ni * 8 + qrow;
                b[ni][0] = Bb[nc * PAD + k8 + qcol];
                b[ni][1] = Bb[nc * PAD + k8 + qcol + 4];
            }
            #pragma unroll
            for (int mi = 0; mi < 4; ++mi)
                #pragma unroll
                for (int ni = 0; ni < 8; ++ni)
                    mma_tf32(acc[mi][ni], a[mi], b[ni]);
        }

        s = (s == 2) ? 0 : s + 1;
        p = (p == 2) ? 0 : p + 1;
    }

    // Epilogue: add bias, float2 stores
    #pragma unroll
    for (int ni = 0; ni < 8; ++ni) {
        const int n = n0 + wn * 64 + ni * 8 + (qcol << 1);
        const float2 bv = *(const float2*)(bias + n);
        #pragma unroll
        for (int mi = 0; mi < 4; ++mi) {
            const int m = m0 + wm * 64 + mi * 16 + qrow;
            float2 o0, o1;
            o0.x = acc[mi][ni][0] + bv.x; o0.y = acc[mi][ni][1] + bv.y;
            o1.x = acc[mi][ni][2] + bv.x; o1.y = acc[mi][ni][3] + bv.y;
            *(float2*)(C + (size_t)m * 512 + n) = o0;
            *(float2*)(C + (size_t)(m + 8) * 512 + n) = o1;
        }
    }
}

// QKV: grid.z selects slot (0,1,2) -> writes slots (3,4,5)
__global__ void __launch_bounds__(128, 2)
gemm_qkv(const float* __restrict__ bq, const float* __restrict__ bk,
         const float* __restrict__ bv)
{
    const int z = blockIdx.z;
    const float* bias = (z == 0) ? bq : (z == 1) ? bk : bv;
    gemm_body(g_scr[z], g_w[z], bias, g_scr[3 + z]);
}

__global__ void __launch_bounds__(128, 2)
gemm_proj(const float* __restrict__ bias, float* __restrict__ C)
{
    gemm_body(g_scr[0], g_w[3], bias, C);
}

// ---------------------------------------------------------------------------
// Kernel 3: tensor-core attention. One block (128 thr, 4 warps) per (b,h).
// ---------------------------------------------------------------------------
__global__ void __launch_bounds__(128)
attn_mma(const float* __restrict__ pos, const float* __restrict__ mask)
{
    const int bh = blockIdx.x;
    const int b = bh >> 4;
    const int h = bh & 15;
    const int tid  = threadIdx.x;
    const int wid  = tid >> 5;
    const int lane = tid & 31;
    const int qrow = lane >> 2;
    const int qcol = lane & 3;

    __shared__ float Qs[64][36];
    __shared__ float Ks[64][36];
    __shared__ float Vt[32][68];       // V transposed [dim][token]
    __shared__ float Ps[4][16][68];    // per-warp P tile

    const float* Q  = g_scr[3];
    const float* Kt = g_scr[4];
    const float* V  = g_scr[5];
    const size_t base = (size_t)b * 64 * 512 + h * 32;

    const float scale = 0.17677669529663687f; // 1/sqrt(32)

    #pragma unroll
    for (int i = tid; i < 512; i += 128) {
        const int t = i >> 3, j = i & 7;
        const size_t g = base + (size_t)t * 512 + j * 4;
        float4 qv = *(const float4*)(Q + g);
        float4 kv = *(const float4*)(Kt + g);
        float4 vv = *(const float4*)(V + g);
        float4 qo;
        qo.x = tf32r(qv.x * scale); qo.y = tf32r(qv.y * scale);
        qo.z = tf32r(qv.z * scale); qo.w = tf32r(qv.w * scale);
        *(float4*)&Qs[t][j * 4] = qo;
        float4 ko;
        ko.x = tf32r(kv.x); ko.y = tf32r(kv.y);
        ko.z = tf32r(kv.z); ko.w = tf32r(kv.w);
        *(float4*)&Ks[t][j * 4] = ko;
        Vt[j * 4 + 0][t] = tf32r(vv.x);
        Vt[j * 4 + 1][t] = tf32r(vv.y);
        Vt[j * 4 + 2][t] = tf32r(vv.z);
        Vt[j * 4 + 3][t] = tf32r(vv.w);
    }
    __syncthreads();

    const int m0 = wid * 16;
    float acc[8][4];
    #pragma unroll
    for (int nt = 0; nt < 8; ++nt)
        #pragma unroll
        for (int r = 0; r < 4; ++r) acc[nt][r] = 0.0f;

    #pragma unroll
    for (int kt = 0; kt < 4; ++kt) {
        const int k8 = kt * 8;
        float a[4];
        a[0] = Qs[m0 + qrow][k8 + qcol];
        a[1] = Qs[m0 + qrow + 8][k8 + qcol];
        a[2] = Qs[m0 + qrow][k8 + qcol + 4];
        a[3] = Qs[m0 + qrow + 8][k8 + qcol + 4];
        #pragma unroll
        for (int nt = 0; nt < 8; ++nt) {
            float b2[2];
            b2[0] = Ks[nt * 8 + qrow][k8 + qcol];
            b2[1] = Ks[nt * 8 + qrow][k8 + qcol + 4];
            mma_tf32(acc[nt], a, b2);
        }
    }

    const int r0 = m0 + qrow, r1 = r0 + 8;
    const int cb = qcol * 2;
    float mx0 = -1e30f, mx1 = -1e30f;
    #pragma unroll
    for (int nt = 0; nt < 8; ++nt) {
        const int col = nt * 8 + cb;
        const float2 p0 = *(const float2*)(pos + r0 * 64 + col);
        const float2 p1 = *(const float2*)(pos + r1 * 64 + col);
        const float2 g0 = *(const float2*)(mask + ((size_t)b * 64 + r0) * 64 + col);
        const float2 g1 = *(const float2*)(mask + ((size_t)b * 64 + r1) * 64 + col);
        acc[nt][0] += p0.x + g0.x;
        acc[nt][1] += p0.y + g0.y;
        acc[nt][2] += p1.x + g1.x;
        acc[nt][3] += p1.y + g1.y;
        mx0 = fmaxf(mx0, fmaxf(acc[nt][0], acc[nt][1]));
        mx1 = fmaxf(mx1, fmaxf(acc[nt][2], acc[nt][3]));
    }
    mx0 = fmaxf(mx0, __shfl_xor_sync(0xffffffffu, mx0, 1));
    mx0 = fmaxf(mx0, __shfl_xor_sync(0xffffffffu, mx0, 2));
    mx1 = fmaxf(mx1, __shfl_xor_sync(0xffffffffu, mx1, 1));
    mx1 = fmaxf(mx1, __shfl_xor_sync(0xffffffffu, mx1, 2));

    float s0 = 0.0f, s1 = 0.0f;
    #pragma unroll
    for (int nt = 0; nt < 8; ++nt) {
        acc[nt][0] = __expf(acc[nt][0] - mx0);
        acc[nt][1] = __expf(acc[nt][1] - mx0);
        acc[nt][2] = __expf(acc[nt][2] - mx1);
        acc[nt][3] = __expf(acc[nt][3] - mx1);
        s0 += acc[nt][0] + acc[nt][1];
        s1 += acc[nt][2] + acc[nt][3];
    }
    s0 += __shfl_xor_sync(0xffffffffu, s0, 1);
    s0 += __shfl_xor_sync(0xffffffffu, s0, 2);
    s1 += __shfl_xor_sync(0xffffffffu, s1, 1);
    s1 += __shfl_xor_sync(0xffffffffu, s1, 2);
    const float inv0 = 1.0f / s0;
    const float inv1 = 1.0f / s1;

    float (*Pw)[68] = Ps[wid];
    #pragma unroll
    for (int nt = 0; nt < 8; ++nt) {
        const int col = nt * 8 + cb;
        *(float2*)&Pw[qrow][col]     = make_float2(tf32r(acc[nt][0]), tf32r(acc[nt][1]));
        *(float2*)&Pw[qrow + 8][col] = make_float2(tf32r(acc[nt][2]), tf32r(acc[nt][3]));
    }
    __syncwarp();

    float oacc[4][4];
    #pragma unroll
    for (int nt = 0; nt < 4; ++nt)
        #pragma unroll
        for (int r = 0; r < 4; ++r) oacc[nt][r] = 0.0f;

    #pragma unroll
    for (int kt = 0; kt < 8; ++kt) {
        const int k8 = kt * 8;
        float a[4];
        a[0] = Pw[qrow][k8 + qcol];
        a[1] = Pw[qrow + 8][k8 + qcol];
        a[2] = Pw[qrow][k8 + qcol + 4];
        a[3] = Pw[qrow + 8][k8 + qcol + 4];
        #pragma unroll
        for (int nt = 0; nt < 4; ++nt) {
            float b2[2];
            b2[0] = Vt[nt * 8 + qrow][k8 + qcol];
            b2[1] = Vt[nt * 8 + qrow][k8 + qcol + 4];
            mma_tf32(oacc[nt], a, b2);
        }
    }

    float* O = g_scr[0] + base;
    #pragma unroll
    for (int nt = 0; nt < 4; ++nt) {
        const int col = nt * 8 + cb;
        float2 w0, w1;
        w0.x = tf32r(oacc[nt][0] * inv0); w0.y = tf32r(oacc[nt][1] * inv0);
        w1.x = tf32r(oacc[nt][2] * inv1); w1.y = tf32r(oacc[nt][3] * inv1);
        *(float2*)(O + (size_t)r0 * 512 + col) = w0;
        *(float2*)(O + (size_t)r1 * 512 + col) = w1;
    }
}

// ---------------------------------------------------------------------------
// Launch
// ---------------------------------------------------------------------------
extern "C" void kernel_launch(void* const* d_in, const int* in_sizes, int n_in,
                              void* d_out, int out_size)
{
    const float* x      = (const float*)d_in[0];
    const float* mask   = (const float*)d_in[1];
    const float* dwq_w  = (const float*)d_in[2];
    const float* dwq_b  = (const float*)d_in[3];
    const float* pwq_w  = (const float*)d_in[4];
    const float* pwq_b  = (const float*)d_in[5];
    const float* dwk_w  = (const float*)d_in[6];
    const float* dwk_b  = (const float*)d_in[7];
    const float* pwk_w  = (const float*)d_in[8];
    const float* pwk_b  = (const float*)d_in[9];
    const float* dwv_w  = (const float*)d_in[10];
    const float* dwv_b  = (const float*)d_in[11];
    const float* pwv_w  = (const float*)d_in[12];
    const float* pwv_b  = (const float*)d_in[13];
    const float* pos    = (const float*)d_in[14];
    const float* proj_w = (const float*)d_in[15];
    const float* proj_b = (const float*)d_in[16];

    cudaFuncSetAttribute(gemm_qkv, cudaFuncAttributeMaxDynamicSharedMemorySize, GSMEM_BYTES);
    cudaFuncSetAttribute(gemm_proj, cudaFuncAttributeMaxDynamicSharedMemorySize, GSMEM_BYTES);

    // 0. round weights to tf32
    prep_w<<<4096, 256>>>(pwq_w, pwk_w, pwv_w, proj_w);

    // 1. depthwise 3x3 + ReLU -> slots 0,1,2
    dim3 gdw(4, BW);
    dw3_kernel<<<gdw, 256>>>(x, dwq_w, dwq_b, dwk_w, dwk_b, dwv_w, dwv_b);

    // 2. pointwise GEMMs (one launch, z = q/k/v) -> slots 3,4,5
    dim3 gqkv(4, 512, 3);
    gemm_qkv<<<gqkv, 128, GSMEM_BYTES>>>(pwq_b, pwk_b, pwv_b);

    // 3. tensor-core attention -> slot 0
    attn_mma<<<BW * HEADS, 128>>>(pos, mask);

    // 4. output projection -> d_out
    dim3 gg(4, 512);
    gemm_proj<<<gg, 128, GSMEM_BYTES>>>(proj_b, (float*)d_out);
}

// round 8
// speedup vs baseline: 5.3393x; 1.5420x over previous
#include <cuda_runtime.h>
#include <cuda_fp16.h>
#include <math.h>
#include <stdint.h>

// Problem constants
#define BW    1024          // windows (batch)
#define NTOK  64            // tokens per window (8x8)
#define CDIM  512           // channels
#define HEADS 16
#define HD    32            // head dim
#define BNC   (BW*NTOK*CDIM)

// Half scratch slots:
// slot 0: dwq -> later attention output
// slot 1: dwk   slot 2: dwv
// slot 3: q (pre-scaled)   slot 4: k     slot 5: v
__device__ __half g_scrh[6][BNC];
// fp16-rounded weights: 0=pwq (pre-scaled by 1/sqrt(32)), 1=pwk, 2=pwv, 3=proj
__device__ __half g_wh[4][CDIM*CDIM];

#define ATTN_SCALE 0.17677669529663687f   // 1/sqrt(32)

// ---------------------------------------------------------------------------
// Weight prep: round 4x [512,512] fp32 weights to fp16; w0 pre-scaled.
// ---------------------------------------------------------------------------
__global__ void prep_w(const float* __restrict__ w0, const float* __restrict__ w1,
                       const float* __restrict__ w2, const float* __restrict__ w3)
{
    int idx = blockIdx.x * 256 + threadIdx.x;    // 4*262144 total
    int w = idx >> 18, j = idx & 262143;
    const float* s = (w == 0) ? w0 : (w == 1) ? w1 : (w == 2) ? w2 : w3;
    float v = s[j];
    if (w == 0) v *= ATTN_SCALE;
    g_wh[w][j] = __float2half_rn(v);
}

// ---------------------------------------------------------------------------
// Kernel 1: fused depthwise 3x3 (+bias, ReLU) for q, k, v (fp16 outputs).
// ---------------------------------------------------------------------------
__global__ void dw3_kernel(const float* __restrict__ x,
                           const float* __restrict__ wq, const float* __restrict__ bq,
                           const float* __restrict__ wk, const float* __restrict__ bk,
                           const float* __restrict__ wv, const float* __restrict__ bv)
{
    const int b   = blockIdx.y;
    const int c0  = blockIdx.x * 128;
    const int tid = threadIdx.x;            // 256 threads

    __shared__ float sx[64][128];
    const float* xb = x + (size_t)b * NTOK * CDIM;

    #pragma unroll
    for (int i = tid; i < 64 * 128; i += 256) {
        int n = i >> 7, c = i & 127;
        sx[n][c] = xb[n * CDIM + c0 + c];
    }
    __syncthreads();

    const int cl   = tid & 127;
    const int c    = c0 + cl;
    const int half = tid >> 7;

    float wqr[9], wkr[9], wvr[9];
    #pragma unroll
    for (int j = 0; j < 9; ++j) {
        wqr[j] = wq[c * 9 + j];
        wkr[j] = wk[c * 9 + j];
        wvr[j] = wv[c * 9 + j];
    }
    const float bqr = bq[c], bkr = bk[c], bvr = bv[c];

    __half* oq = g_scrh[0] + (size_t)b * NTOK * CDIM;
    __half* ok = g_scrh[1] + (size_t)b * NTOK * CDIM;
    __half* ov = g_scrh[2] + (size_t)b * NTOK * CDIM;

    #pragma unroll 4
    for (int nn = 0; nn < 32; ++nn) {
        int n = half * 32 + nn;
        int l = n >> 3, w = n & 7;
        float aq = bqr, ak = bkr, av = bvr;
        #pragma unroll
        for (int dl = -1; dl <= 1; ++dl) {
            #pragma unroll
            for (int dw = -1; dw <= 1; ++dw) {
                int ll = l + dl, ww = w + dw;
                if (ll < 0 || ll > 7 || ww < 0 || ww > 7) continue;
                float xv = sx[ll * 8 + ww][cl];
                int j = (dl + 1) * 3 + (dw + 1);
                aq += xv * wqr[j];
                ak += xv * wkr[j];
                av += xv * wvr[j];
            }
        }
        int idx = n * CDIM + c;
        oq[idx] = __float2half_rn(fmaxf(aq, 0.0f));
        ok[idx] = __float2half_rn(fmaxf(ak, 0.0f));
        ov[idx] = __float2half_rn(fmaxf(av, 0.0f));
    }
}

// ---------------------------------------------------------------------------
// mma.sync fp16 helpers (f32 accumulate)
// ---------------------------------------------------------------------------
__device__ __forceinline__ void mma_f16(float* d, uint32_t a0, uint32_t a1,
                                        uint32_t a2, uint32_t a3,
                                        uint32_t b0, uint32_t b1)
{
    asm volatile(
        "mma.sync.aligned.m16n8k16.row.col.f32.f16.f16.f32 "
        "{%0,%1,%2,%3}, {%4,%5,%6,%7}, {%8,%9}, {%0,%1,%2,%3};"
        : "+f"(d[0]), "+f"(d[1]), "+f"(d[2]), "+f"(d[3])
        : "r"(a0), "r"(a1), "r"(a2), "r"(a3), "r"(b0), "r"(b1));
}

__device__ __forceinline__ void cp16(uint32_t dst, const void* src)
{
    asm volatile("cp.async.cg.shared.global [%0], [%1], 16;"
                 :: "r"(dst), "l"(src) : "memory");
}

__device__ __forceinline__ uint32_t pack_h2(float lo, float hi)
{
    __half2 h = __floats2half2_rn(lo, hi);
    return *(uint32_t*)&h;
}

// ---------------------------------------------------------------------------
// fp16 GEMM body: C[65536,512] = A @ W^T + bias
// CTA 128x128, 128 threads = 4 warps (2x2), warp tile 64x64, m16n8k16.
// K-chunk 16 (one MMA depth), 3-stage cp.async ring, one sync per chunk.
// Smem rows = 8 half2 data + pad -> pitch 12 half2 (bank-conflict-free frags).
// ---------------------------------------------------------------------------
#define PADH 12
#define HST  (128 * PADH)                 // half2 (=u32) per stage per matrix

__device__ __forceinline__ void gemm_body_h(const __half* __restrict__ A,
                                            const __half* __restrict__ W,
                                            const float* __restrict__ bias,
                                            float bscale,
                                            __half* __restrict__ Ch,
                                            float* __restrict__ Cf)
{
    __shared__ uint32_t smA[3 * HST];
    __shared__ uint32_t smB[3 * HST];

    const int tid  = threadIdx.x;           // 128 threads
    const int wid  = tid >> 5;
    const int lane = tid & 31;
    const int wm   = wid & 1;
    const int wn   = wid >> 1;
    const int m0 = blockIdx.y * 128;
    const int n0 = blockIdx.x * 128;

    const int lrow = tid >> 1;              // 0..63
    const int seg  = tid & 1;               // 8-half segment within k16

    const int qrow = lane >> 2;
    const int qcol = lane & 3;

    const uint32_t sAb = (uint32_t)__cvta_generic_to_shared(smA);
    const uint32_t sBb = (uint32_t)__cvta_generic_to_shared(smB);

    float acc[4][8][4];
    #pragma unroll
    for (int i = 0; i < 4; ++i)
        #pragma unroll
        for (int j = 0; j < 8; ++j)
            #pragma unroll
            for (int r = 0; r < 4; ++r) acc[i][j][r] = 0.0f;

    const __half* Ap = A + (size_t)(m0 + lrow) * 512 + seg * 8;
    const __half* Bp = W + (size_t)(n0 + lrow) * 512 + seg * 8;

    // prologue: stages 0,1
    #pragma unroll
    for (int st = 0; st < 2; ++st) {
        #pragma unroll
        for (int r = 0; r < 2; ++r) {
            uint32_t off = (uint32_t)(((st * 128 + lrow + r * 64) * PADH + seg * 4) * 4);
            cp16(sAb + off, Ap + (size_t)(r * 64) * 512 + st * 16);
            cp16(sBb + off, Bp + (size_t)(r * 64) * 512 + st * 16);
        }
        asm volatile("cp.async.commit_group;" ::: "memory");
    }

    int s = 0, p = 2;
    #pragma unroll 1
    for (int ch = 0; ch < 32; ++ch) {
        asm volatile("cp.async.wait_group 1;" ::: "memory");
        __syncthreads();

        if (ch < 30) {
            const int kb = (ch + 2) * 16;
            #pragma unroll
            for (int r = 0; r < 2; ++r) {
                uint32_t off = (uint32_t)(((p * 128 + lrow + r * 64) * PADH + seg * 4) * 4);
                cp16(sAb + off, Ap + (size_t)(r * 64) * 512 + kb);
                cp16(sBb + off, Bp + (size_t)(r * 64) * 512 + kb);
            }
        }
        asm volatile("cp.async.commit_group;" ::: "memory");

        const uint32_t* Ab = smA + s * HST;
        const uint32_t* Bb = smB + s * HST;

        uint32_t a[4][4];
        #pragma unroll
        for (int mi = 0; mi < 4; ++mi) {
            const int mr = wm * 64 + mi * 16 + qrow;
            a[mi][0] = Ab[mr * PADH + qcol];
            a[mi][1] = Ab[(mr + 8) * PADH + qcol];
            a[mi][2] = Ab[mr * PADH + qcol + 4];
            a[mi][3] = Ab[(mr + 8) * PADH + qcol + 4];
        }
        uint32_t bfr[8][2];
        #pragma unroll
        for (int ni = 0; ni < 8; ++ni) {
            const int nc = wn * 64 + ni * 8 + qrow;
            bfr[ni][0] = Bb[nc * PADH + qcol];
            bfr[ni][1] = Bb[nc * PADH + qcol + 4];
        }
        #pragma unroll
        for (int mi = 0; mi < 4; ++mi)
            #pragma unroll
            for (int ni = 0; ni < 8; ++ni)
                mma_f16(acc[mi][ni], a[mi][0], a[mi][1], a[mi][2], a[mi][3],
                        bfr[ni][0], bfr[ni][1]);

        s = (s == 2) ? 0 : s + 1;
        p = (p == 2) ? 0 : p + 1;
    }

    // Epilogue: bias (optionally scaled), half2 or float2 stores
    #pragma unroll
    for (int ni = 0; ni < 8; ++ni) {
        const int n = n0 + wn * 64 + ni * 8 + (qcol << 1);
        const float bx = bias[n] * bscale;
        const float by = bias[n + 1] * bscale;
        #pragma unroll
        for (int mi = 0; mi < 4; ++mi) {
            const int m = m0 + wm * 64 + mi * 16 + qrow;
            const float f0 = acc[mi][ni][0] + bx, f1 = acc[mi][ni][1] + by;
            const float f2 = acc[mi][ni][2] + bx, f3 = acc[mi][ni][3] + by;
            if (Ch) {
                *(uint32_t*)(Ch + (size_t)m * 512 + n)       = pack_h2(f0, f1);
                *(uint32_t*)(Ch + (size_t)(m + 8) * 512 + n) = pack_h2(f2, f3);
            } else {
                *(float2*)(Cf + (size_t)m * 512 + n)       = make_float2(f0, f1);
                *(float2*)(Cf + (size_t)(m + 8) * 512 + n) = make_float2(f2, f3);
            }
        }
    }
}

// QKV: grid.z selects slot (0,1,2) -> writes slots (3,4,5).
// z==0 bias is scaled by ATTN_SCALE (weights already pre-scaled in prep_w).
__global__ void __launch_bounds__(128, 3)
gemm_qkv(const float* __restrict__ bq, const float* __restrict__ bk,
         const float* __restrict__ bv)
{
    const int z = blockIdx.z;
    const float* bias = (z == 0) ? bq : (z == 1) ? bk : bv;
    const float bscale = (z == 0) ? ATTN_SCALE : 1.0f;
    gemm_body_h(g_scrh[z], g_wh[z], bias, bscale, g_scrh[3 + z], nullptr);
}

__global__ void __launch_bounds__(128, 3)
gemm_proj(const float* __restrict__ bias, float* __restrict__ C)
{
    gemm_body_h(g_scrh[0], g_wh[3], bias, 1.0f, nullptr, C);
}

// ---------------------------------------------------------------------------
// Kernel 3: fp16 tensor-core attention. One block (128 thr, 4 warps) per (b,h).
// S = Q K^T (m16n8k16, 2 k-chunks), f32 softmax with pos+mask, P packed to
// half2, O = P V (4 k-chunks). q arrives pre-scaled.
// Smem pitches: Q/K 20 half2/row, V^T & P 36 half2/row (bank-verified).
// ---------------------------------------------------------------------------
__global__ void __launch_bounds__(128)
attn_h(const float* __restrict__ pos, const float* __restrict__ mask)
{
    const int bh = blockIdx.x;
    const int b = bh >> 4;
    const int h = bh & 15;
    const int tid  = threadIdx.x;
    const int wid  = tid >> 5;
    const int lane = tid & 31;
    const int qrow = lane >> 2;
    const int qcol = lane & 3;

    __shared__ uint32_t Qs[64 * 20];      // [token][16 half2 + pad]
    __shared__ uint32_t Ks[64 * 20];
    __shared__ uint32_t Vt[32 * 36];      // [dim][32 half2 tokens + pad]
    __shared__ uint32_t Ps[4][16 * 36];   // per-warp P tile

    const __half* Q = g_scrh[3];
    const __half* K = g_scrh[4];
    const __half* V = g_scrh[5];
    const size_t base = (size_t)b * 64 * 512 + h * 32;

    // Stage Q, K (row-major half2) and V^T (transposed, half stores).
    __half* Vth = (__half*)Vt;
    #pragma unroll
    for (int i = tid; i < 256; i += 128) {
        const int t = i >> 2, g = i & 3;       // token, uint4 group (8 halves)
        const size_t gofs = base + (size_t)t * 512 + g * 8;
        uint4 qv = *(const uint4*)(Q + gofs);
        uint4 kv = *(const uint4*)(K + gofs);
        uint4 vv = *(const uint4*)(V + gofs);
        Qs[t * 20 + g * 4 + 0] = qv.x; Qs[t * 20 + g * 4 + 1] = qv.y;
        Qs[t * 20 + g * 4 + 2] = qv.z; Qs[t * 20 + g * 4 + 3] = qv.w;
        Ks[t * 20 + g * 4 + 0] = kv.x; Ks[t * 20 + g * 4 + 1] = kv.y;
        Ks[t * 20 + g * 4 + 2] = kv.z; Ks[t * 20 + g * 4 + 3] = kv.w;
        const __half* vh = (const __half*)&vv;
        #pragma unroll
        for (int k = 0; k < 8; ++k)
            Vth[(g * 8 + k) * 72 + t] = vh[k];
    }
    __syncthreads();

    // S = Q K^T  (warp rows m0..m0+15)
    const int m0 = wid * 16;
    float acc[8][4];
    #pragma unroll
    for (int nt = 0; nt < 8; ++nt)
        #pragma unroll
        for (int r = 0; r < 4; ++r) acc[nt][r] = 0.0f;

    #pragma unroll
    for (int kt = 0; kt < 2; ++kt) {
        const int kb = kt * 8;
        uint32_t a0 = Qs[(m0 + qrow) * 20 + kb + qcol];
        uint32_t a1 = Qs[(m0 + qrow + 8) * 20 + kb + qcol];
        uint32_t a2 = Qs[(m0 + qrow) * 20 + kb + qcol + 4];
        uint32_t a3 = Qs[(m0 + qrow + 8) * 20 + kb + qcol + 4];
        #pragma unroll
        for (int nt = 0; nt < 8; ++nt) {
            uint32_t b0 = Ks[(nt * 8 + qrow) * 20 + kb + qcol];
            uint32_t b1 = Ks[(nt * 8 + qrow) * 20 + kb + qcol + 4];
            mma_f16(acc[nt], a0, a1, a2, a3, b0, b1);
        }
    }

    // pos + mask, fragment softmax (quad shfl reductions)
    const int r0 = m0 + qrow, r1 = r0 + 8;
    const int cb = qcol * 2;
    float mx0 = -1e30f, mx1 = -1e30f;
    #pragma unroll
    for (int nt = 0; nt < 8; ++nt) {
        const int col = nt * 8 + cb;
        const float2 p0 = *(const float2*)(pos + r0 * 64 + col);
        const float2 p1 = *(const float2*)(pos + r1 * 64 + col);
        const float2 g0 = *(const float2*)(mask + ((size_t)b * 64 + r0) * 64 + col);
        const float2 g1 = *(const float2*)(mask + ((size_t)b * 64 + r1) * 64 + col);
        acc[nt][0] += p0.x + g0.x;
        acc[nt][1] += p0.y + g0.y;
        acc[nt][2] += p1.x + g1.x;
        acc[nt][3] += p1.y + g1.y;
        mx0 = fmaxf(mx0, fmaxf(acc[nt][0], acc[nt][1]));
        mx1 = fmaxf(mx1, fmaxf(acc[nt][2], acc[nt][3]));
    }
    mx0 = fmaxf(mx0, __shfl_xor_sync(0xffffffffu, mx0, 1));
    mx0 = fmaxf(mx0, __shfl_xor_sync(0xffffffffu, mx0, 2));
    mx1 = fmaxf(mx1, __shfl_xor_sync(0xffffffffu, mx1, 1));
    mx1 = fmaxf(mx1, __shfl_xor_sync(0xffffffffu, mx1, 2));

    float s0 = 0.0f, s1 = 0.0f;
    #pragma unroll
    for (int nt = 0; nt < 8; ++nt) {
        acc[nt][0] = __expf(acc[nt][0] - mx0);
        acc[nt][1] = __expf(acc[nt][1] - mx0);
        acc[nt][2] = __expf(acc[nt][2] - mx1);
        acc[nt][3] = __expf(acc[nt][3] - mx1);
        s0 += acc[nt][0] + acc[nt][1];
        s1 += acc[nt][2] + acc[nt][3];
    }
    s0 += __shfl_xor_sync(0xffffffffu, s0, 1);
    s0 += __shfl_xor_sync(0xffffffffu, s0, 2);
    s1 += __shfl_xor_sync(0xffffffffu, s1, 1);
    s1 += __shfl_xor_sync(0xffffffffu, s1, 2);
    const float inv0 = 1.0f / s0;
    const float inv1 = 1.0f / s1;

    // P (unnormalized) to half2 smem — C-fragment cols are adjacent pairs
    uint32_t* Pw = Ps[wid];
    #pragma unroll
    for (int nt = 0; nt < 8; ++nt) {
        const int c2 = nt * 4 + qcol;
        Pw[qrow * 36 + c2]       = pack_h2(acc[nt][0], acc[nt][1]);
        Pw[(qrow + 8) * 36 + c2] = pack_h2(acc[nt][2], acc[nt][3]);
    }
    __syncwarp();

    // O = P V  (K = 64 tokens = 4 k16 chunks, N = 32 dims)
    float oacc[4][4];
    #pragma unroll
    for (int nt = 0; nt < 4; ++nt)
        #pragma unroll
        for (int r = 0; r < 4; ++r) oacc[nt][r] = 0.0f;

    #pragma unroll
    for (int kt = 0; kt < 4; ++kt) {
        const int kb = kt * 8;
        uint32_t a0 = Pw[qrow * 36 + kb + qcol];
        uint32_t a1 = Pw[(qrow + 8) * 36 + kb + qcol];
        uint32_t a2 = Pw[qrow * 36 + kb + qcol + 4];
        uint32_t a3 = Pw[(qrow + 8) * 36 + kb + qcol + 4];
        #pragma unroll
        for (int nt = 0; nt < 4; ++nt) {
            uint32_t b0 = Vt[(nt * 8 + qrow) * 36 + kb + qcol];
            uint32_t b1 = Vt[(nt * 8 + qrow) * 36 + kb + qcol + 4];
            mma_f16(oacc[nt], a0, a1, a2, a3, b0, b1);
        }
    }

    // normalize, pack to half2, store to slot 0 at [token][h*32+dim]
    __half* O = g_scrh[0] + base;
    #pragma unroll
    for (int nt = 0; nt < 4; ++nt) {
        const int col = nt * 8 + cb;
        *(uint32_t*)(O + (size_t)r0 * 512 + col) =
            pack_h2(oacc[nt][0] * inv0, oacc[nt][1] * inv0);
        *(uint32_t*)(O + (size_t)r1 * 512 + col) =
            pack_h2(oacc[nt][2] * inv1, oacc[nt][3] * inv1);
    }
}

// ---------------------------------------------------------------------------
// Launch
// ---------------------------------------------------------------------------
extern "C" void kernel_launch(void* const* d_in, const int* in_sizes, int n_in,
                              void* d_out, int out_size)
{
    const float* x      = (const float*)d_in[0];
    const float* mask   = (const float*)d_in[1];
    const float* dwq_w  = (const float*)d_in[2];
    const float* dwq_b  = (const float*)d_in[3];
    const float* pwq_w  = (const float*)d_in[4];
    const float* pwq_b  = (const float*)d_in[5];
    const float* dwk_w  = (const float*)d_in[6];
    const float* dwk_b  = (const float*)d_in[7];
    const float* pwk_w  = (const float*)d_in[8];
    const float* pwk_b  = (const float*)d_in[9];
    const float* dwv_w  = (const float*)d_in[10];
    const float* dwv_b  = (const float*)d_in[11];
    const float* pwv_w  = (const float*)d_in[12];
    const float* pwv_b  = (const float*)d_in[13];
    const float* pos    = (const float*)d_in[14];
    const float* proj_w = (const float*)d_in[15];
    const float* proj_b = (const float*)d_in[16];

    // 0. round weights to fp16 (w0 pre-scaled by attention scale)
    prep_w<<<4096, 256>>>(pwq_w, pwk_w, pwv_w, proj_w);

    // 1. depthwise 3x3 + ReLU -> slots 0,1,2 (fp16)
    dim3 gdw(4, BW);
    dw3_kernel<<<gdw, 256>>>(x, dwq_w, dwq_b, dwk_w, dwk_b, dwv_w, dwv_b);

    // 2. pointwise GEMMs (fp16 mma) -> slots 3,4,5
    dim3 gqkv(4, 512, 3);
    gemm_qkv<<<gqkv, 128>>>(pwq_b, pwk_b, pwv_b);

    // 3. fp16 tensor-core attention -> slot 0
    attn_h<<<BW * HEADS, 128>>>(pos, mask);

    // 4. output projection -> d_out (f32)
    dim3 gg(4, 512);
    gemm_proj<<<gg, 128>>>(proj_b, (float*)d_out);
}